// round 14
// baseline (speedup 1.0000x reference)
#include <cuda_runtime.h>
#include <cuda_bf16.h>
#include <math.h>
#include <stdint.h>

// Problem constants: feat [65536, 256], n_per_graph = 512 -> B = 128, d = 256.
#define NB   128
#define NPG  512
#define DIM  256
#define DD   (DIM*DIM)
#define BD   (NB*DD)
#define NOISE_RATE 0.01f

// Scratch (allocation-free rule: device globals)
__device__ float g_A[BD];      // A = cov/trace (fp32), preserved
__device__ float g_DTh[BD];    // bf16 [B][DIM][NPG]: diff^T hi
__device__ float g_DTm[BD];    // bf16 [B][DIM][NPG]: diff^T lo
__device__ float g_X2[BD];     // M^2 scratch
__device__ float g_M0[BD];     // M ping
__device__ float g_M1[BD];     // M pong
__device__ float g_mean[NB*DIM];
__device__ float g_va[NB*DIM];
__device__ float g_vb[NB*DIM];
__device__ float g_w1[NB*DIM];
__device__ float g_w2[NB*DIM];
__device__ float g_w3[NB*DIM];
__device__ float g_v5[NB*DIM];
__device__ float g_norm[NB];
__device__ float g_psum[NB*4*DIM];
__device__ float g_psq[NB*4*DIM];

// ---------------------------------------------------------------------------
// helpers
// ---------------------------------------------------------------------------
__device__ __forceinline__ uint32_t smem_u32(const void* p) {
    uint32_t a;
    asm("{ .reg .u64 t; cvta.to.shared.u64 t, %1; cvt.u32.u64 %0, t; }" : "=r"(a) : "l"(p));
    return a;
}
__device__ __forceinline__ void ldm4(uint32_t* r, uint32_t a) {
    asm volatile("ldmatrix.sync.aligned.m8n8.x4.shared.b16 {%0,%1,%2,%3}, [%4];"
                 : "=r"(r[0]), "=r"(r[1]), "=r"(r[2]), "=r"(r[3]) : "r"(a));
}
__device__ __forceinline__ void mma16816(float* c, const uint32_t* a, const uint32_t* bq) {
    asm volatile("mma.sync.aligned.m16n8k16.row.col.f32.bf16.bf16.f32 "
                 "{%0,%1,%2,%3}, {%4,%5,%6,%7}, {%8,%9}, {%0,%1,%2,%3};"
                 : "+f"(c[0]), "+f"(c[1]), "+f"(c[2]), "+f"(c[3])
                 : "r"(a[0]), "r"(a[1]), "r"(a[2]), "r"(a[3]), "r"(bq[0]), "r"(bq[1]));
}
// bf16 2-term split of 4 floats -> packed h (2x u32) and m (2x u32)
__device__ __forceinline__ void split4(float4 v, uint32_t& h0, uint32_t& h1,
                                       uint32_t& q0, uint32_t& q1) {
    __nv_bfloat16 a = __float2bfloat16_rn(v.x);
    __nv_bfloat16 bb = __float2bfloat16_rn(v.y);
    __nv_bfloat16 c = __float2bfloat16_rn(v.z);
    __nv_bfloat16 d = __float2bfloat16_rn(v.w);
    __nv_bfloat162 hl; hl.x = a;  hl.y = bb;
    __nv_bfloat162 hh; hh.x = c;  hh.y = d;
    h0 = *(uint32_t*)&hl; h1 = *(uint32_t*)&hh;
    __nv_bfloat16 ma = __float2bfloat16_rn(v.x - __bfloat162float(a));
    __nv_bfloat16 mb = __float2bfloat16_rn(v.y - __bfloat162float(bb));
    __nv_bfloat16 mc = __float2bfloat16_rn(v.z - __bfloat162float(c));
    __nv_bfloat16 md = __float2bfloat16_rn(v.w - __bfloat162float(d));
    __nv_bfloat162 ml; ml.x = ma; ml.y = mb;
    __nv_bfloat162 mh; mh.x = mc; mh.y = md;
    q0 = *(uint32_t*)&ml; q1 = *(uint32_t*)&mh;
}

// symmetric-output tile map: 6 tiles cover the 2x4 (BM=128 x BN=64) grid of a
// 256x256 symmetric matrix. Tiles 2,3 are strictly upper -> mirror into lower.
__device__ __forceinline__ void sym_tile(int bx, int& mi, int& nj, int& mirror) {
    mi = (bx >= 4) ? 1 : 0;
    nj = (bx >= 4) ? (bx - 2) : bx;
    mirror = (bx == 2 || bx == 3) ? 1 : 0;
}

// ---------------------------------------------------------------------------
// mean stage 1: grid (4, NB), block 256: partial sum + sumsq over 128 nodes
// ---------------------------------------------------------------------------
__global__ void mean_part(const float* __restrict__ feat,
                          const float* __restrict__ noise) {
    int b = blockIdx.y, p = blockIdx.x, c = threadIdx.x;
    const float* F  = feat  + ((size_t)b * NPG + p * 128) * DIM + c;
    const float* Nz = noise + ((size_t)b * NPG + p * 128) * DIM + c;
    float s = 0.f, q = 0.f;
    #pragma unroll 8
    for (int n = 0; n < 128; ++n) {
        float v = F[(size_t)n * DIM] + NOISE_RATE * Nz[(size_t)n * DIM];
        s += v; q += v * v;
    }
    g_psum[(b * 4 + p) * DIM + c] = s;
    g_psq [(b * 4 + p) * DIM + c] = q;
}

// mean stage 2: grid NB, block 256: finalize mean + trace
__global__ void mean_final() {
    int b = blockIdx.x, c = threadIdx.x;
    float s = 0.f, q = 0.f;
    #pragma unroll
    for (int p = 0; p < 4; ++p) {
        s += g_psum[(b * 4 + p) * DIM + c];
        q += g_psq [(b * 4 + p) * DIM + c];
    }
    float m = s * (1.f / NPG);
    g_mean[b * DIM + c] = m;
    float t = q - (float)NPG * m * m;
    #pragma unroll
    for (int o = 16; o; o >>= 1) t += __shfl_xor_sync(0xffffffffu, t, o);
    __shared__ float sm[8];
    if ((c & 31) == 0) sm[c >> 5] = t;
    __syncthreads();
    if (c == 0) {
        float tot = 0.f;
        #pragma unroll
        for (int w = 0; w < 8; w++) tot += sm[w];
        g_norm[b] = tot * (1.f / (NPG - 1));
    }
}

// ---------------------------------------------------------------------------
// prep: diff^T split to bf16 (h, m), transposed to [b][dim][node].
// ---------------------------------------------------------------------------
__global__ void prep_kernel(const float* __restrict__ feat,
                            const float* __restrict__ noise,
                            __nv_bfloat16* __restrict__ DTh,
                            __nv_bfloat16* __restrict__ DTm) {
    int b = blockIdx.z;
    int n0 = blockIdx.x * 32, d0 = blockIdx.y * 32;
    __shared__ float t[32][33];
    __shared__ float mn[32];
    int tid = threadIdx.x;
    if (tid < 32) mn[tid] = g_mean[b * DIM + d0 + tid];
    __syncthreads();
    {
        int n = tid >> 3, dq = (tid & 7) * 4;
        size_t off = ((size_t)(b * NPG + n0 + n)) * DIM + d0 + dq;
        float4 f = *(const float4*)&feat[off];
        float4 z = *(const float4*)&noise[off];
        t[n][dq + 0] = f.x + NOISE_RATE * z.x - mn[dq + 0];
        t[n][dq + 1] = f.y + NOISE_RATE * z.y - mn[dq + 1];
        t[n][dq + 2] = f.z + NOISE_RATE * z.z - mn[dq + 2];
        t[n][dq + 3] = f.w + NOISE_RATE * z.w - mn[dq + 3];
    }
    __syncthreads();
    {
        int d = tid >> 3, nq = (tid & 7) * 4;
        float4 v = make_float4(t[nq + 0][d], t[nq + 1][d], t[nq + 2][d], t[nq + 3][d]);
        uint32_t h0, h1, m0, m1;
        split4(v, h0, h1, m0, m1);
        size_t off = ((size_t)(b * DIM + d0 + d)) * NPG + n0 + nq;
        *(uint2*)&DTh[off] = make_uint2(h0, h1);
        *(uint2*)&DTm[off] = make_uint2(m0, m1);
    }
}

// ---------------------------------------------------------------------------
// shared GEMM geometry (proven round-9)
// ---------------------------------------------------------------------------
#define BM 128
#define BN 64
#define RSTRIDE 80
#define OFF_AH 0
#define OFF_AM (BM * RSTRIDE)
#define OFF_BH (2 * BM * RSTRIDE)
#define OFF_BM (2 * BM * RSTRIDE + BN * RSTRIDE)
#define SMEM_GEMM (2 * BM * RSTRIDE + 2 * BN * RSTRIDE)

#define GEMM_FRAG_SETUP()                                                         \
    uint32_t aAd[2];                                                              \
    _Pragma("unroll")                                                             \
    for (int mt = 0; mt < 2; mt++)                                                \
        aAd[mt] = sb + OFF_AH + (uint32_t)(wm + mt * 16 + (lane & 15)) * RSTRIDE  \
                + ((lane >> 4) & 1) * 16;                                         \
    uint32_t bAd[2];                                                              \
    _Pragma("unroll")                                                             \
    for (int p = 0; p < 2; p++)                                                   \
        bAd[p] = sb + OFF_BH + (uint32_t)(wn + p * 16 + (lane & 7) + ((lane >> 4) & 1) * 8) * RSTRIDE \
               + ((lane >> 3) & 1) * 16;

#define GEMM_MAINLOOP_CHUNK()                                                     \
    _Pragma("unroll")                                                             \
    for (int kk = 0; kk < 2; kk++) {                                              \
        uint32_t ah[2][4], am[2][4];                                              \
        _Pragma("unroll")                                                         \
        for (int mt = 0; mt < 2; mt++) {                                          \
            ldm4(ah[mt], aAd[mt] + kk * 32);                                      \
            ldm4(am[mt], aAd[mt] + kk * 32 + (OFF_AM - OFF_AH));                  \
        }                                                                         \
        {                                                                         \
            uint32_t bb[2][4];                                                    \
            _Pragma("unroll")                                                     \
            for (int p = 0; p < 2; p++) ldm4(bb[p], bAd[p] + kk * 32);            \
            _Pragma("unroll")                                                     \
            for (int mt = 0; mt < 2; mt++)                                        \
                _Pragma("unroll")                                                 \
                for (int nt = 0; nt < 4; nt++) {                                  \
                    mma16816(acc[mt][nt], ah[mt], &bb[nt >> 1][(nt & 1) * 2]);    \
                    mma16816(acc[mt][nt], am[mt], &bb[nt >> 1][(nt & 1) * 2]);    \
                }                                                                 \
        }                                                                         \
        {                                                                         \
            uint32_t bb[2][4];                                                    \
            _Pragma("unroll")                                                     \
            for (int p = 0; p < 2; p++) ldm4(bb[p], bAd[p] + kk * 32 + (OFF_BM - OFF_BH)); \
            _Pragma("unroll")                                                     \
            for (int mt = 0; mt < 2; mt++)                                        \
                _Pragma("unroll")                                                 \
                for (int nt = 0; nt < 4; nt++)                                    \
                    mma16816(acc[mt][nt], ah[mt], &bb[nt >> 1][(nt & 1) * 2]);    \
        }                                                                         \
    }

// ---------------------------------------------------------------------------
// batched symmetric 256x256x256 GEMM via bf16 split (round-9 proven).
// mode 0: C = A@B.  mode 1: C = 2.25*P - 1.5*Q + 0.25*(A@B)
// ---------------------------------------------------------------------------
__global__ void __launch_bounds__(256, 2) gemm_bf16(const float* __restrict__ Ag,
                                                    const float* __restrict__ Bg,
                                                    float* __restrict__ Cg,
                                                    const float* __restrict__ Pg,
                                                    const float* __restrict__ Qg,
                                                    int mode) {
    __shared__ char smem[SMEM_GEMM];
    const uint32_t sb = smem_u32(smem);
    const int tid = threadIdx.x, lane = tid & 31, wid = tid >> 5;
    const int b = blockIdx.z;
    int mi, nj, mirror;
    sym_tile(blockIdx.x, mi, nj, mirror);
    const int m0 = mi * BM, n0 = nj * BN;
    const int wm = (wid & 3) * 32, wn = (wid >> 2) * 32;
    const float* A  = Ag + (size_t)b * DD;
    const float* Bm = Bg + (size_t)b * DD;

    const int srow = tid >> 3, skq = tid & 7;
    const float* gA = A  + (size_t)(m0 + srow) * DIM + skq * 4;
    const float* gB = Bm + (size_t)(n0 + srow) * DIM + skq * 4;
    const uint32_t stOff = (uint32_t)srow * RSTRIDE + skq * 8;

    GEMM_FRAG_SETUP();

    float acc[2][4][4];
    #pragma unroll
    for (int mt = 0; mt < 2; mt++)
        #pragma unroll
        for (int nt = 0; nt < 4; nt++)
            #pragma unroll
            for (int k = 0; k < 4; k++) acc[mt][nt][k] = 0.f;

    float4 pa[4], pb[2];
    #pragma unroll
    for (int p = 0; p < 4; p++) pa[p] = *(const float4*)(gA + (size_t)p * 32 * DIM);
    #pragma unroll
    for (int p = 0; p < 2; p++) pb[p] = *(const float4*)(gB + (size_t)p * 32 * DIM);

    for (int kc = 0; kc < 8; ++kc) {
        #pragma unroll
        for (int p = 0; p < 4; p++) {
            uint32_t h0, h1, q0, q1;
            split4(pa[p], h0, h1, q0, q1);
            uint32_t ad = stOff + p * 32 * RSTRIDE;
            *((uint2*)(smem + ad + OFF_AH)) = make_uint2(h0, h1);
            *((uint2*)(smem + ad + OFF_AM)) = make_uint2(q0, q1);
        }
        #pragma unroll
        for (int p = 0; p < 2; p++) {
            uint32_t h0, h1, q0, q1;
            split4(pb[p], h0, h1, q0, q1);
            uint32_t ad = stOff + p * 32 * RSTRIDE;
            *((uint2*)(smem + ad + OFF_BH)) = make_uint2(h0, h1);
            *((uint2*)(smem + ad + OFF_BM)) = make_uint2(q0, q1);
        }
        __syncthreads();
        if (kc < 7) {
            #pragma unroll
            for (int p = 0; p < 4; p++) pa[p] = *(const float4*)(gA + (size_t)p * 32 * DIM + (kc + 1) * 32);
            #pragma unroll
            for (int p = 0; p < 2; p++) pb[p] = *(const float4*)(gB + (size_t)p * 32 * DIM + (kc + 1) * 32);
        }
        GEMM_MAINLOOP_CHUNK();
        __syncthreads();
    }

    float* C = Cg + (size_t)b * DD;
    const float* P = Pg + (size_t)b * DD;
    const float* Q = Qg + (size_t)b * DD;
    int rr = m0 + wm + (lane >> 2);
    int cc = n0 + wn + (lane & 3) * 2;
    #pragma unroll
    for (int mt = 0; mt < 2; mt++) {
        #pragma unroll
        for (int nt = 0; nt < 4; nt++) {
            int r = rr + mt * 16, c = cc + nt * 8;
            float v0 = acc[mt][nt][0], v1 = acc[mt][nt][1];
            float v2 = acc[mt][nt][2], v3 = acc[mt][nt][3];
            if (mode == 1) {
                float2 p0 = *(const float2*)&P[(size_t)r * DIM + c];
                float2 p1 = *(const float2*)&P[(size_t)(r + 8) * DIM + c];
                float2 q0 = *(const float2*)&Q[(size_t)r * DIM + c];
                float2 q1 = *(const float2*)&Q[(size_t)(r + 8) * DIM + c];
                v0 = 2.25f * p0.x - 1.5f * q0.x + 0.25f * v0;
                v1 = 2.25f * p0.y - 1.5f * q0.y + 0.25f * v1;
                v2 = 2.25f * p1.x - 1.5f * q1.x + 0.25f * v2;
                v3 = 2.25f * p1.y - 1.5f * q1.y + 0.25f * v3;
            }
            *(float2*)&C[(size_t)r * DIM + c]       = make_float2(v0, v1);
            *(float2*)&C[(size_t)(r + 8) * DIM + c] = make_float2(v2, v3);
            if (mirror) {
                C[(size_t)(c + 0) * DIM + r]     = v0;
                C[(size_t)(c + 1) * DIM + r]     = v1;
                C[(size_t)(c + 0) * DIM + r + 8] = v2;
                C[(size_t)(c + 1) * DIM + r + 8] = v3;
            }
        }
    }
}

// ---------------------------------------------------------------------------
// covariance GEMM: A = (diff^T @ diff) / ((N-1)*trace), K = 512. Symmetric.
// ---------------------------------------------------------------------------
__global__ void __launch_bounds__(256, 2) cov_mma(const __nv_bfloat16* __restrict__ DTh,
                                                  const __nv_bfloat16* __restrict__ DTm,
                                                  float* __restrict__ Cg) {
    __shared__ char smem[SMEM_GEMM];
    const uint32_t sb = smem_u32(smem);
    const int tid = threadIdx.x, lane = tid & 31, wid = tid >> 5;
    const int b = blockIdx.z;
    int mi, nj, mirror;
    sym_tile(blockIdx.x, mi, nj, mirror);
    const int m0 = mi * BM, n0 = nj * BN;
    const int wm = (wid & 3) * 32, wn = (wid >> 2) * 32;

    const int lrow = tid >> 2, lq = tid & 3;
    const __nv_bfloat16* baseH = DTh + (size_t)b * DIM * NPG;
    const __nv_bfloat16* baseM = DTm + (size_t)b * DIM * NPG;

    GEMM_FRAG_SETUP();

    float acc[2][4][4];
    #pragma unroll
    for (int mt = 0; mt < 2; mt++)
        #pragma unroll
        for (int nt = 0; nt < 4; nt++)
            #pragma unroll
            for (int k = 0; k < 4; k++) acc[mt][nt][k] = 0.f;

    uint4 pAh[2], pAm[2], pBh, pBm;
    {
        size_t a0 = (size_t)(m0 + lrow) * NPG + lq * 8;
        size_t a1 = (size_t)(m0 + 64 + lrow) * NPG + lq * 8;
        size_t b0 = (size_t)(n0 + lrow) * NPG + lq * 8;
        pAh[0] = *(const uint4*)(baseH + a0); pAm[0] = *(const uint4*)(baseM + a0);
        pAh[1] = *(const uint4*)(baseH + a1); pAm[1] = *(const uint4*)(baseM + a1);
        pBh    = *(const uint4*)(baseH + b0); pBm    = *(const uint4*)(baseM + b0);
    }

    for (int kc = 0; kc < 16; ++kc) {
        {
            uint32_t ad0 = (uint32_t)lrow * RSTRIDE + lq * 16;
            uint32_t ad1 = (uint32_t)(64 + lrow) * RSTRIDE + lq * 16;
            *((uint4*)(smem + ad0 + OFF_AH)) = pAh[0];
            *((uint4*)(smem + ad0 + OFF_AM)) = pAm[0];
            *((uint4*)(smem + ad1 + OFF_AH)) = pAh[1];
            *((uint4*)(smem + ad1 + OFF_AM)) = pAm[1];
            *((uint4*)(smem + ad0 + OFF_BH)) = pBh;
            *((uint4*)(smem + ad0 + OFF_BM)) = pBm;
        }
        __syncthreads();
        if (kc < 15) {
            size_t ko = (size_t)(kc + 1) * 32 + lq * 8;
            size_t a0 = (size_t)(m0 + lrow) * NPG + ko;
            size_t a1 = (size_t)(m0 + 64 + lrow) * NPG + ko;
            size_t b0 = (size_t)(n0 + lrow) * NPG + ko;
            pAh[0] = *(const uint4*)(baseH + a0); pAm[0] = *(const uint4*)(baseM + a0);
            pAh[1] = *(const uint4*)(baseH + a1); pAm[1] = *(const uint4*)(baseM + a1);
            pBh    = *(const uint4*)(baseH + b0); pBm    = *(const uint4*)(baseM + b0);
        }
        GEMM_MAINLOOP_CHUNK();
        __syncthreads();
    }

    float* C = Cg + (size_t)b * DD;
    const float sc = 1.f / ((NPG - 1) * g_norm[b]);
    int rr = m0 + wm + (lane >> 2);
    int cc = n0 + wn + (lane & 3) * 2;
    #pragma unroll
    for (int mt = 0; mt < 2; mt++) {
        #pragma unroll
        for (int nt = 0; nt < 4; nt++) {
            int r = rr + mt * 16, c = cc + nt * 8;
            float v0 = acc[mt][nt][0] * sc, v1 = acc[mt][nt][1] * sc;
            float v2 = acc[mt][nt][2] * sc, v3 = acc[mt][nt][3] * sc;
            *(float2*)&C[(size_t)r * DIM + c]       = make_float2(v0, v1);
            *(float2*)&C[(size_t)(r + 8) * DIM + c] = make_float2(v2, v3);
            if (mirror) {
                C[(size_t)(c + 0) * DIM + r]     = v0;
                C[(size_t)(c + 1) * DIM + r]     = v1;
                C[(size_t)(c + 0) * DIM + r + 8] = v2;
                C[(size_t)(c + 1) * DIM + r + 8] = v3;
            }
        }
    }
}

// ---------------------------------------------------------------------------
// generalized matvec:
// vout[b,r] = scale * ( c0*x0 + c1*x1 + c2*x2 + c3*x3 + alpha*vin + beta*(M@vin) )
// grid (8, NB). vin != vout (ping-pong). aux reads only on the writing lane.
// ---------------------------------------------------------------------------
__global__ void matvec_kernel(const float* __restrict__ M,
                              const float* __restrict__ vin,
                              float* __restrict__ vout,
                              const float* __restrict__ x0,
                              const float* __restrict__ x1,
                              const float* __restrict__ x2,
                              const float* __restrict__ x3,
                              float c0, float c1, float c2, float c3,
                              float alpha, float beta, int useScale) {
    int b = blockIdx.y;
    int r0 = blockIdx.x * 32;
    __shared__ float vs[DIM];
    int tid = threadIdx.x;
    vs[tid] = vin[b * DIM + tid];
    __syncthreads();
    int warp = tid >> 5, lane = tid & 31;
    int r = r0 + warp * 4 + (lane >> 3);
    int c0i = (lane & 7) * 32;
    const float* Mr = M + (size_t)b * DD + (size_t)r * DIM + c0i;
    float s = 0.f;
    #pragma unroll
    for (int c = 0; c < 32; c += 4) {
        float4 mv = *(const float4*)(Mr + c);
        s += mv.x * vs[c0i + c] + mv.y * vs[c0i + c + 1]
           + mv.z * vs[c0i + c + 2] + mv.w * vs[c0i + c + 3];
    }
    #pragma unroll
    for (int o = 4; o; o >>= 1) s += __shfl_xor_sync(0xffffffffu, s, o);
    if ((lane & 7) == 0) {
        float scale = useScale ? sqrtf(g_norm[b]) : 1.f;
        int gi = b * DIM + r;
        float extra = c0 * x0[gi] + c1 * x1[gi] + c2 * x2[gi] + c3 * x3[gi];
        vout[gi] = scale * (extra + alpha * vs[r] + beta * s);
    }
}

// ---------------------------------------------------------------------------
extern "C" void kernel_launch(void* const* d_in, const int* in_sizes, int n_in,
                              void* d_out, int out_size) {
    const float* feat  = (const float*)d_in[0];
    const float* noise = (const float*)d_in[1];
    float* out = (float*)d_out;

    float *A, *DTh, *DTm, *X2, *M0, *M1, *Mean, *Va, *Vb, *W1, *W2, *W3, *V5;
    cudaGetSymbolAddress((void**)&A,    g_A);
    cudaGetSymbolAddress((void**)&DTh,  g_DTh);
    cudaGetSymbolAddress((void**)&DTm,  g_DTm);
    cudaGetSymbolAddress((void**)&X2,   g_X2);
    cudaGetSymbolAddress((void**)&M0,   g_M0);
    cudaGetSymbolAddress((void**)&M1,   g_M1);
    cudaGetSymbolAddress((void**)&Mean, g_mean);
    cudaGetSymbolAddress((void**)&Va,   g_va);
    cudaGetSymbolAddress((void**)&Vb,   g_vb);
    cudaGetSymbolAddress((void**)&W1,   g_w1);
    cudaGetSymbolAddress((void**)&W2,   g_w2);
    cudaGetSymbolAddress((void**)&W3,   g_w3);
    cudaGetSymbolAddress((void**)&V5,   g_v5);

    mean_part<<<dim3(4, NB), 256>>>(feat, noise);
    mean_final<<<NB, 256>>>();
    prep_kernel<<<dim3(NPG / 32, DIM / 32, NB), 256>>>(feat, noise,
        (__nv_bfloat16*)DTh, (__nv_bfloat16*)DTm);
    cov_mma<<<dim3(6, 1, NB), 256>>>(
        (const __nv_bfloat16*)DTh, (const __nv_bfloat16*)DTm, A);

    dim3 mv(8, NB);
    // plain matvec helper coefficients: aux unused -> pass vin with coeff 0
    #define MV(Mx, in, outp, al, be, sc) \
        matvec_kernel<<<mv, 256>>>(Mx, in, outp, in, in, in, in, 0.f, 0.f, 0.f, 0.f, al, be, sc)

    // v1 = 1.5*mean - 0.5*A@mean
    MV(A, Mean, Va, 1.5f, -0.5f, 0);

    // k = 0,1: M_{k+1} = f(M_k); v <- 1.5v - 0.5*M_{k+1}v
    dim3 gg(6, 1, NB);
    float* Mcur = A;
    float* Mbuf[2] = {M0, M1};
    float* Vbuf[2] = {Va, Vb};
    int vc = 0;
    for (int k = 0; k < 2; ++k) {
        float* Mnext = Mbuf[k & 1];
        gemm_bf16<<<gg, 256>>>(Mcur, Mcur, X2, A, A, 0);      // X2 = M@M
        gemm_bf16<<<gg, 256>>>(X2, Mcur, Mnext, Mcur, X2, 1); // M' = f(M)
        MV(Mnext, Vbuf[vc], Vbuf[1 - vc], 1.5f, -0.5f, 0);
        vc ^= 1;
        Mcur = Mnext;
    }
    // Now Mcur = M2, v (= v3 chain value) in Vbuf[vc]. Remaining factors M3, M4
    // applied purely via matvecs:  M3 x = 2.25 u1 - 1.5 u2 + 0.25 M2 u2.
    float* v = Vbuf[vc];
    float* v4 = Vbuf[1 - vc];

    // v4 = 1.5v - 0.5*M3 v = 1.5v - 1.125u1 + 0.75u2 - 0.125*M2 u2
    MV(Mcur, v,  W1, 0.f, 1.f, 0);                            // u1 = M2 v
    MV(Mcur, W1, W2, 0.f, 1.f, 0);                            // u2 = M2 u1
    matvec_kernel<<<mv, 256>>>(Mcur, W2, v4, v, W1, W2, W2,
                               1.5f, -1.125f, 0.75f, 0.f, 0.f, -0.125f, 0);

    // w1 = M3 v4
    MV(Mcur, v4, W1, 0.f, 1.f, 0);                            // t1
    MV(Mcur, W1, W2, 0.f, 1.f, 0);                            // t2
    matvec_kernel<<<mv, 256>>>(Mcur, W2, W3, W1, W2, W2, W2,
                               2.25f, -1.5f, 0.f, 0.f, 0.f, 0.25f, 0);  // w1 -> W3

    // w2 = M3 w1
    MV(Mcur, W3, W1, 0.f, 1.f, 0);                            // t1'
    MV(Mcur, W1, W2, 0.f, 1.f, 0);                            // t2'
    matvec_kernel<<<mv, 256>>>(Mcur, W2, v, W1, W2, W2, W2,
                               2.25f, -1.5f, 0.f, 0.f, 0.f, 0.25f, 0);  // w2 -> v (old v buffer)

    // w3 chain + final fold:
    // v5 = 1.5v4 - 1.125w1 + 0.75w2 - 0.28125t1'' + 0.1875t2'' - 0.03125*M2 t2''
    MV(Mcur, v,  W1, 0.f, 1.f, 0);                            // t1'' = M2 w2
    MV(Mcur, W1, W2, 0.f, 1.f, 0);                            // t2'' = M2 t1''
    matvec_kernel<<<mv, 256>>>(Mcur, W2, V5, v4, W3, v, W1,
                               1.5f, -1.125f, 0.75f, -0.28125f,
                               0.1875f, -0.03125f, 0);

    // out = sqrt(trace) * A @ v5
    MV(A, V5, out, 0.f, 1.f, 1);
    #undef MV
}

// round 15
// speedup vs baseline: 1.1952x; 1.1952x over previous
#include <cuda_runtime.h>
#include <cuda_bf16.h>
#include <math.h>
#include <stdint.h>

// Problem constants: feat [65536, 256], n_per_graph = 512 -> B = 128, d = 256.
#define NB   128
#define NPG  512
#define DIM  256
#define DD   (DIM*DIM)
#define BD   (NB*DD)
#define NOISE_RATE 0.01f

// Scratch (allocation-free rule: device globals)
__device__ float g_A[BD];      // A = cov/trace (fp32), preserved
__device__ float g_DTh[BD];    // bf16 [B][DIM][NPG]: diff^T hi
__device__ float g_DTm[BD];    // bf16 [B][DIM][NPG]: diff^T lo
__device__ float g_X2[BD];     // M^2 scratch
__device__ float g_M0[BD];     // M ping
__device__ float g_M1[BD];     // M pong
__device__ float g_mean[NB*DIM];
__device__ float g_va[NB*DIM];
__device__ float g_vb[NB*DIM];
__device__ float g_norm[NB];
__device__ float g_psum[NB*4*DIM];
__device__ float g_psq[NB*4*DIM];

// ---------------------------------------------------------------------------
// helpers
// ---------------------------------------------------------------------------
__device__ __forceinline__ uint32_t smem_u32(const void* p) {
    uint32_t a;
    asm("{ .reg .u64 t; cvta.to.shared.u64 t, %1; cvt.u32.u64 %0, t; }" : "=r"(a) : "l"(p));
    return a;
}
__device__ __forceinline__ void ldm4(uint32_t* r, uint32_t a) {
    asm volatile("ldmatrix.sync.aligned.m8n8.x4.shared.b16 {%0,%1,%2,%3}, [%4];"
                 : "=r"(r[0]), "=r"(r[1]), "=r"(r[2]), "=r"(r[3]) : "r"(a));
}
__device__ __forceinline__ void mma16816(float* c, const uint32_t* a, const uint32_t* bq) {
    asm volatile("mma.sync.aligned.m16n8k16.row.col.f32.bf16.bf16.f32 "
                 "{%0,%1,%2,%3}, {%4,%5,%6,%7}, {%8,%9}, {%0,%1,%2,%3};"
                 : "+f"(c[0]), "+f"(c[1]), "+f"(c[2]), "+f"(c[3])
                 : "r"(a[0]), "r"(a[1]), "r"(a[2]), "r"(a[3]), "r"(bq[0]), "r"(bq[1]));
}
// bf16 2-term split of 4 floats -> packed h (2x u32) and m (2x u32)
__device__ __forceinline__ void split4(float4 v, uint32_t& h0, uint32_t& h1,
                                       uint32_t& q0, uint32_t& q1) {
    __nv_bfloat16 a = __float2bfloat16_rn(v.x);
    __nv_bfloat16 bb = __float2bfloat16_rn(v.y);
    __nv_bfloat16 c = __float2bfloat16_rn(v.z);
    __nv_bfloat16 d = __float2bfloat16_rn(v.w);
    __nv_bfloat162 hl; hl.x = a;  hl.y = bb;
    __nv_bfloat162 hh; hh.x = c;  hh.y = d;
    h0 = *(uint32_t*)&hl; h1 = *(uint32_t*)&hh;
    __nv_bfloat16 ma = __float2bfloat16_rn(v.x - __bfloat162float(a));
    __nv_bfloat16 mb = __float2bfloat16_rn(v.y - __bfloat162float(bb));
    __nv_bfloat16 mc = __float2bfloat16_rn(v.z - __bfloat162float(c));
    __nv_bfloat16 md = __float2bfloat16_rn(v.w - __bfloat162float(d));
    __nv_bfloat162 ml; ml.x = ma; ml.y = mb;
    __nv_bfloat162 mh; mh.x = mc; mh.y = md;
    q0 = *(uint32_t*)&ml; q1 = *(uint32_t*)&mh;
}

// symmetric-output tile map: 6 tiles cover the 2x4 (BM=128 x BN=64) grid of a
// 256x256 symmetric matrix. Tiles 2,3 are strictly upper -> mirror into lower.
__device__ __forceinline__ void sym_tile(int bx, int& mi, int& nj, int& mirror) {
    mi = (bx >= 4) ? 1 : 0;
    nj = (bx >= 4) ? (bx - 2) : bx;
    mirror = (bx == 2 || bx == 3) ? 1 : 0;
}

// ---------------------------------------------------------------------------
// mean stage 1: grid (4, NB), block 256: partial sum + sumsq over 128 nodes
// ---------------------------------------------------------------------------
__global__ void mean_part(const float* __restrict__ feat,
                          const float* __restrict__ noise) {
    int b = blockIdx.y, p = blockIdx.x, c = threadIdx.x;
    const float* F  = feat  + ((size_t)b * NPG + p * 128) * DIM + c;
    const float* Nz = noise + ((size_t)b * NPG + p * 128) * DIM + c;
    float s = 0.f, q = 0.f;
    #pragma unroll 8
    for (int n = 0; n < 128; ++n) {
        float v = F[(size_t)n * DIM] + NOISE_RATE * Nz[(size_t)n * DIM];
        s += v; q += v * v;
    }
    g_psum[(b * 4 + p) * DIM + c] = s;
    g_psq [(b * 4 + p) * DIM + c] = q;
}

// mean stage 2: grid NB, block 256: finalize mean + trace
__global__ void mean_final() {
    int b = blockIdx.x, c = threadIdx.x;
    float s = 0.f, q = 0.f;
    #pragma unroll
    for (int p = 0; p < 4; ++p) {
        s += g_psum[(b * 4 + p) * DIM + c];
        q += g_psq [(b * 4 + p) * DIM + c];
    }
    float m = s * (1.f / NPG);
    g_mean[b * DIM + c] = m;
    float t = q - (float)NPG * m * m;
    #pragma unroll
    for (int o = 16; o; o >>= 1) t += __shfl_xor_sync(0xffffffffu, t, o);
    __shared__ float sm[8];
    if ((c & 31) == 0) sm[c >> 5] = t;
    __syncthreads();
    if (c == 0) {
        float tot = 0.f;
        #pragma unroll
        for (int w = 0; w < 8; w++) tot += sm[w];
        g_norm[b] = tot * (1.f / (NPG - 1));
    }
}

// ---------------------------------------------------------------------------
// prep: diff^T split to bf16 (h, m), transposed to [b][dim][node].
// ---------------------------------------------------------------------------
__global__ void prep_kernel(const float* __restrict__ feat,
                            const float* __restrict__ noise,
                            __nv_bfloat16* __restrict__ DTh,
                            __nv_bfloat16* __restrict__ DTm) {
    int b = blockIdx.z;
    int n0 = blockIdx.x * 32, d0 = blockIdx.y * 32;
    __shared__ float t[32][33];
    __shared__ float mn[32];
    int tid = threadIdx.x;
    if (tid < 32) mn[tid] = g_mean[b * DIM + d0 + tid];
    __syncthreads();
    {
        int n = tid >> 3, dq = (tid & 7) * 4;
        size_t off = ((size_t)(b * NPG + n0 + n)) * DIM + d0 + dq;
        float4 f = *(const float4*)&feat[off];
        float4 z = *(const float4*)&noise[off];
        t[n][dq + 0] = f.x + NOISE_RATE * z.x - mn[dq + 0];
        t[n][dq + 1] = f.y + NOISE_RATE * z.y - mn[dq + 1];
        t[n][dq + 2] = f.z + NOISE_RATE * z.z - mn[dq + 2];
        t[n][dq + 3] = f.w + NOISE_RATE * z.w - mn[dq + 3];
    }
    __syncthreads();
    {
        int d = tid >> 3, nq = (tid & 7) * 4;
        float4 v = make_float4(t[nq + 0][d], t[nq + 1][d], t[nq + 2][d], t[nq + 3][d]);
        uint32_t h0, h1, m0, m1;
        split4(v, h0, h1, m0, m1);
        size_t off = ((size_t)(b * DIM + d0 + d)) * NPG + n0 + nq;
        *(uint2*)&DTh[off] = make_uint2(h0, h1);
        *(uint2*)&DTm[off] = make_uint2(m0, m1);
    }
}

// ---------------------------------------------------------------------------
// shared GEMM geometry (proven round-9)
// ---------------------------------------------------------------------------
#define BM 128
#define BN 64
#define RSTRIDE 80
#define OFF_AH 0
#define OFF_AM (BM * RSTRIDE)
#define OFF_BH (2 * BM * RSTRIDE)
#define OFF_BM (2 * BM * RSTRIDE + BN * RSTRIDE)
#define SMEM_GEMM (2 * BM * RSTRIDE + 2 * BN * RSTRIDE)

#define GEMM_FRAG_SETUP()                                                         \
    uint32_t aAd[2];                                                              \
    _Pragma("unroll")                                                             \
    for (int mt = 0; mt < 2; mt++)                                                \
        aAd[mt] = sb + OFF_AH + (uint32_t)(wm + mt * 16 + (lane & 15)) * RSTRIDE  \
                + ((lane >> 4) & 1) * 16;                                         \
    uint32_t bAd[2];                                                              \
    _Pragma("unroll")                                                             \
    for (int p = 0; p < 2; p++)                                                   \
        bAd[p] = sb + OFF_BH + (uint32_t)(wn + p * 16 + (lane & 7) + ((lane >> 4) & 1) * 8) * RSTRIDE \
               + ((lane >> 3) & 1) * 16;

#define GEMM_MAINLOOP_CHUNK()                                                     \
    _Pragma("unroll")                                                             \
    for (int kk = 0; kk < 2; kk++) {                                              \
        uint32_t ah[2][4], am[2][4];                                              \
        _Pragma("unroll")                                                         \
        for (int mt = 0; mt < 2; mt++) {                                          \
            ldm4(ah[mt], aAd[mt] + kk * 32);                                      \
            ldm4(am[mt], aAd[mt] + kk * 32 + (OFF_AM - OFF_AH));                  \
        }                                                                         \
        {                                                                         \
            uint32_t bb[2][4];                                                    \
            _Pragma("unroll")                                                     \
            for (int p = 0; p < 2; p++) ldm4(bb[p], bAd[p] + kk * 32);            \
            _Pragma("unroll")                                                     \
            for (int mt = 0; mt < 2; mt++)                                        \
                _Pragma("unroll")                                                 \
                for (int nt = 0; nt < 4; nt++) {                                  \
                    mma16816(acc[mt][nt], ah[mt], &bb[nt >> 1][(nt & 1) * 2]);    \
                    mma16816(acc[mt][nt], am[mt], &bb[nt >> 1][(nt & 1) * 2]);    \
                }                                                                 \
        }                                                                         \
        {                                                                         \
            uint32_t bb[2][4];                                                    \
            _Pragma("unroll")                                                     \
            for (int p = 0; p < 2; p++) ldm4(bb[p], bAd[p] + kk * 32 + (OFF_BM - OFF_BH)); \
            _Pragma("unroll")                                                     \
            for (int mt = 0; mt < 2; mt++)                                        \
                _Pragma("unroll")                                                 \
                for (int nt = 0; nt < 4; nt++)                                    \
                    mma16816(acc[mt][nt], ah[mt], &bb[nt >> 1][(nt & 1) * 2]);    \
        }                                                                         \
    }

// ---------------------------------------------------------------------------
// batched symmetric 256x256x256 GEMM via bf16 split (round-9 proven).
// mode 0: C = A@B.  mode 1: C = 2.25*P - 1.5*Q + 0.25*(A@B)
// ---------------------------------------------------------------------------
__global__ void __launch_bounds__(256, 2) gemm_bf16(const float* __restrict__ Ag,
                                                    const float* __restrict__ Bg,
                                                    float* __restrict__ Cg,
                                                    const float* __restrict__ Pg,
                                                    const float* __restrict__ Qg,
                                                    int mode) {
    __shared__ char smem[SMEM_GEMM];
    const uint32_t sb = smem_u32(smem);
    const int tid = threadIdx.x, lane = tid & 31, wid = tid >> 5;
    const int b = blockIdx.z;
    int mi, nj, mirror;
    sym_tile(blockIdx.x, mi, nj, mirror);
    const int m0 = mi * BM, n0 = nj * BN;
    const int wm = (wid & 3) * 32, wn = (wid >> 2) * 32;
    const float* A  = Ag + (size_t)b * DD;
    const float* Bm = Bg + (size_t)b * DD;

    const int srow = tid >> 3, skq = tid & 7;
    const float* gA = A  + (size_t)(m0 + srow) * DIM + skq * 4;
    const float* gB = Bm + (size_t)(n0 + srow) * DIM + skq * 4;
    const uint32_t stOff = (uint32_t)srow * RSTRIDE + skq * 8;

    GEMM_FRAG_SETUP();

    float acc[2][4][4];
    #pragma unroll
    for (int mt = 0; mt < 2; mt++)
        #pragma unroll
        for (int nt = 0; nt < 4; nt++)
            #pragma unroll
            for (int k = 0; k < 4; k++) acc[mt][nt][k] = 0.f;

    float4 pa[4], pb[2];
    #pragma unroll
    for (int p = 0; p < 4; p++) pa[p] = *(const float4*)(gA + (size_t)p * 32 * DIM);
    #pragma unroll
    for (int p = 0; p < 2; p++) pb[p] = *(const float4*)(gB + (size_t)p * 32 * DIM);

    for (int kc = 0; kc < 8; ++kc) {
        #pragma unroll
        for (int p = 0; p < 4; p++) {
            uint32_t h0, h1, q0, q1;
            split4(pa[p], h0, h1, q0, q1);
            uint32_t ad = stOff + p * 32 * RSTRIDE;
            *((uint2*)(smem + ad + OFF_AH)) = make_uint2(h0, h1);
            *((uint2*)(smem + ad + OFF_AM)) = make_uint2(q0, q1);
        }
        #pragma unroll
        for (int p = 0; p < 2; p++) {
            uint32_t h0, h1, q0, q1;
            split4(pb[p], h0, h1, q0, q1);
            uint32_t ad = stOff + p * 32 * RSTRIDE;
            *((uint2*)(smem + ad + OFF_BH)) = make_uint2(h0, h1);
            *((uint2*)(smem + ad + OFF_BM)) = make_uint2(q0, q1);
        }
        __syncthreads();
        if (kc < 7) {
            #pragma unroll
            for (int p = 0; p < 4; p++) pa[p] = *(const float4*)(gA + (size_t)p * 32 * DIM + (kc + 1) * 32);
            #pragma unroll
            for (int p = 0; p < 2; p++) pb[p] = *(const float4*)(gB + (size_t)p * 32 * DIM + (kc + 1) * 32);
        }
        GEMM_MAINLOOP_CHUNK();
        __syncthreads();
    }

    float* C = Cg + (size_t)b * DD;
    const float* P = Pg + (size_t)b * DD;
    const float* Q = Qg + (size_t)b * DD;
    int rr = m0 + wm + (lane >> 2);
    int cc = n0 + wn + (lane & 3) * 2;
    #pragma unroll
    for (int mt = 0; mt < 2; mt++) {
        #pragma unroll
        for (int nt = 0; nt < 4; nt++) {
            int r = rr + mt * 16, c = cc + nt * 8;
            float v0 = acc[mt][nt][0], v1 = acc[mt][nt][1];
            float v2 = acc[mt][nt][2], v3 = acc[mt][nt][3];
            if (mode == 1) {
                float2 p0 = *(const float2*)&P[(size_t)r * DIM + c];
                float2 p1 = *(const float2*)&P[(size_t)(r + 8) * DIM + c];
                float2 q0 = *(const float2*)&Q[(size_t)r * DIM + c];
                float2 q1 = *(const float2*)&Q[(size_t)(r + 8) * DIM + c];
                v0 = 2.25f * p0.x - 1.5f * q0.x + 0.25f * v0;
                v1 = 2.25f * p0.y - 1.5f * q0.y + 0.25f * v1;
                v2 = 2.25f * p1.x - 1.5f * q1.x + 0.25f * v2;
                v3 = 2.25f * p1.y - 1.5f * q1.y + 0.25f * v3;
            }
            *(float2*)&C[(size_t)r * DIM + c]       = make_float2(v0, v1);
            *(float2*)&C[(size_t)(r + 8) * DIM + c] = make_float2(v2, v3);
            if (mirror) {
                C[(size_t)(c + 0) * DIM + r]     = v0;
                C[(size_t)(c + 1) * DIM + r]     = v1;
                C[(size_t)(c + 0) * DIM + r + 8] = v2;
                C[(size_t)(c + 1) * DIM + r + 8] = v3;
            }
        }
    }
}

// ---------------------------------------------------------------------------
// covariance GEMM: A = (diff^T @ diff) / ((N-1)*trace), K = 512. Symmetric.
// ---------------------------------------------------------------------------
__global__ void __launch_bounds__(256, 2) cov_mma(const __nv_bfloat16* __restrict__ DTh,
                                                  const __nv_bfloat16* __restrict__ DTm,
                                                  float* __restrict__ Cg) {
    __shared__ char smem[SMEM_GEMM];
    const uint32_t sb = smem_u32(smem);
    const int tid = threadIdx.x, lane = tid & 31, wid = tid >> 5;
    const int b = blockIdx.z;
    int mi, nj, mirror;
    sym_tile(blockIdx.x, mi, nj, mirror);
    const int m0 = mi * BM, n0 = nj * BN;
    const int wm = (wid & 3) * 32, wn = (wid >> 2) * 32;

    const int lrow = tid >> 2, lq = tid & 3;
    const __nv_bfloat16* baseH = DTh + (size_t)b * DIM * NPG;
    const __nv_bfloat16* baseM = DTm + (size_t)b * DIM * NPG;

    GEMM_FRAG_SETUP();

    float acc[2][4][4];
    #pragma unroll
    for (int mt = 0; mt < 2; mt++)
        #pragma unroll
        for (int nt = 0; nt < 4; nt++)
            #pragma unroll
            for (int k = 0; k < 4; k++) acc[mt][nt][k] = 0.f;

    uint4 pAh[2], pAm[2], pBh, pBm;
    {
        size_t a0 = (size_t)(m0 + lrow) * NPG + lq * 8;
        size_t a1 = (size_t)(m0 + 64 + lrow) * NPG + lq * 8;
        size_t b0 = (size_t)(n0 + lrow) * NPG + lq * 8;
        pAh[0] = *(const uint4*)(baseH + a0); pAm[0] = *(const uint4*)(baseM + a0);
        pAh[1] = *(const uint4*)(baseH + a1); pAm[1] = *(const uint4*)(baseM + a1);
        pBh    = *(const uint4*)(baseH + b0); pBm    = *(const uint4*)(baseM + b0);
    }

    for (int kc = 0; kc < 16; ++kc) {
        {
            uint32_t ad0 = (uint32_t)lrow * RSTRIDE + lq * 16;
            uint32_t ad1 = (uint32_t)(64 + lrow) * RSTRIDE + lq * 16;
            *((uint4*)(smem + ad0 + OFF_AH)) = pAh[0];
            *((uint4*)(smem + ad0 + OFF_AM)) = pAm[0];
            *((uint4*)(smem + ad1 + OFF_AH)) = pAh[1];
            *((uint4*)(smem + ad1 + OFF_AM)) = pAm[1];
            *((uint4*)(smem + ad0 + OFF_BH)) = pBh;
            *((uint4*)(smem + ad0 + OFF_BM)) = pBm;
        }
        __syncthreads();
        if (kc < 15) {
            size_t ko = (size_t)(kc + 1) * 32 + lq * 8;
            size_t a0 = (size_t)(m0 + lrow) * NPG + ko;
            size_t a1 = (size_t)(m0 + 64 + lrow) * NPG + ko;
            size_t b0 = (size_t)(n0 + lrow) * NPG + ko;
            pAh[0] = *(const uint4*)(baseH + a0); pAm[0] = *(const uint4*)(baseM + a0);
            pAh[1] = *(const uint4*)(baseH + a1); pAm[1] = *(const uint4*)(baseM + a1);
            pBh    = *(const uint4*)(baseH + b0); pBm    = *(const uint4*)(baseM + b0);
        }
        GEMM_MAINLOOP_CHUNK();
        __syncthreads();
    }

    float* C = Cg + (size_t)b * DD;
    const float sc = 1.f / ((NPG - 1) * g_norm[b]);
    int rr = m0 + wm + (lane >> 2);
    int cc = n0 + wn + (lane & 3) * 2;
    #pragma unroll
    for (int mt = 0; mt < 2; mt++) {
        #pragma unroll
        for (int nt = 0; nt < 4; nt++) {
            int r = rr + mt * 16, c = cc + nt * 8;
            float v0 = acc[mt][nt][0] * sc, v1 = acc[mt][nt][1] * sc;
            float v2 = acc[mt][nt][2] * sc, v3 = acc[mt][nt][3] * sc;
            *(float2*)&C[(size_t)r * DIM + c]       = make_float2(v0, v1);
            *(float2*)&C[(size_t)(r + 8) * DIM + c] = make_float2(v2, v3);
            if (mirror) {
                C[(size_t)(c + 0) * DIM + r]     = v0;
                C[(size_t)(c + 1) * DIM + r]     = v1;
                C[(size_t)(c + 0) * DIM + r + 8] = v2;
                C[(size_t)(c + 1) * DIM + r + 8] = v3;
            }
        }
    }
}

// ---------------------------------------------------------------------------
// matvec: vout[b] = scale * (alpha*vin[b] + beta*(M[b] @ vin[b]))
// grid (8, NB). vin != vout (ping-pong).
// ---------------------------------------------------------------------------
__global__ void matvec_kernel(const float* __restrict__ M,
                              const float* __restrict__ vin,
                              float* __restrict__ vout,
                              float alpha, float beta, int useScale) {
    int b = blockIdx.y;
    int r0 = blockIdx.x * 32;
    __shared__ float vs[DIM];
    int tid = threadIdx.x;
    vs[tid] = vin[b * DIM + tid];
    __syncthreads();
    int warp = tid >> 5, lane = tid & 31;
    int r = r0 + warp * 4 + (lane >> 3);
    int c0 = (lane & 7) * 32;
    const float* Mr = M + (size_t)b * DD + (size_t)r * DIM + c0;
    float s = 0.f;
    #pragma unroll
    for (int c = 0; c < 32; c += 4) {
        float4 mv = *(const float4*)(Mr + c);
        s += mv.x * vs[c0 + c] + mv.y * vs[c0 + c + 1]
           + mv.z * vs[c0 + c + 2] + mv.w * vs[c0 + c + 3];
    }
    #pragma unroll
    for (int o = 4; o; o >>= 1) s += __shfl_xor_sync(0xffffffffu, s, o);
    if ((lane & 7) == 0) {
        float scale = useScale ? sqrtf(g_norm[b]) : 1.f;
        vout[b * DIM + r] = scale * (alpha * vs[r] + beta * s);
    }
}

// ---------------------------------------------------------------------------
// block-local matvec: ws = Mb @ xs (256x256), 256 threads, smem vectors.
// warp handles 4 rows per pass (8 lanes per row), 8 passes.
// ---------------------------------------------------------------------------
__device__ __forceinline__ void block_matvec(const float* __restrict__ Mb,
                                             const float* __restrict__ xs,
                                             float* __restrict__ ws, int tid) {
    int warp = tid >> 5, lane = tid & 31;
    #pragma unroll
    for (int pass = 0; pass < 8; ++pass) {
        int r = pass * 32 + warp * 4 + (lane >> 3);
        int c0 = (lane & 7) * 32;
        const float* Mr = Mb + (size_t)r * DIM + c0;
        float s = 0.f;
        #pragma unroll
        for (int c = 0; c < 32; c += 4) {
            float4 mv = *(const float4*)(Mr + c);
            s += mv.x * xs[c0 + c] + mv.y * xs[c0 + c + 1]
               + mv.z * xs[c0 + c + 2] + mv.w * xs[c0 + c + 3];
        }
        #pragma unroll
        for (int o = 4; o; o >>= 1) s += __shfl_xor_sync(0xffffffffu, s, o);
        if ((lane & 7) == 0) ws[r] = s;
    }
}

// ---------------------------------------------------------------------------
// fused tail: one block per batch.
// w1 = M3 v; w2 = M3 w1; w3 = M3 w2;
// v5 = 1.5v - 1.125w1 + 0.75w2 - 0.125w3;  out = sqrt(norm) * A @ v5
// ---------------------------------------------------------------------------
__global__ void tail_kernel(const float* __restrict__ M,
                            const float* __restrict__ A,
                            const float* __restrict__ vin,
                            float* __restrict__ out) {
    int b = blockIdx.x, tid = threadIdx.x;
    __shared__ float v0[DIM], w1[DIM], w2[DIM], w3[DIM], x5[DIM];
    const float* Mb = M + (size_t)b * DD;
    const float* Ab = A + (size_t)b * DD;
    v0[tid] = vin[b * DIM + tid];
    __syncthreads();
    block_matvec(Mb, v0, w1, tid); __syncthreads();
    block_matvec(Mb, w1, w2, tid); __syncthreads();
    block_matvec(Mb, w2, w3, tid); __syncthreads();
    x5[tid] = 1.5f * v0[tid] - 1.125f * w1[tid] + 0.75f * w2[tid] - 0.125f * w3[tid];
    __syncthreads();
    block_matvec(Ab, x5, w1, tid); __syncthreads();
    out[b * DIM + tid] = sqrtf(g_norm[b]) * w1[tid];
}

// ---------------------------------------------------------------------------
extern "C" void kernel_launch(void* const* d_in, const int* in_sizes, int n_in,
                              void* d_out, int out_size) {
    const float* feat  = (const float*)d_in[0];
    const float* noise = (const float*)d_in[1];
    float* out = (float*)d_out;

    float *A, *DTh, *DTm, *X2, *M0, *M1, *Mean, *Va, *Vb;
    cudaGetSymbolAddress((void**)&A,    g_A);
    cudaGetSymbolAddress((void**)&DTh,  g_DTh);
    cudaGetSymbolAddress((void**)&DTm,  g_DTm);
    cudaGetSymbolAddress((void**)&X2,   g_X2);
    cudaGetSymbolAddress((void**)&M0,   g_M0);
    cudaGetSymbolAddress((void**)&M1,   g_M1);
    cudaGetSymbolAddress((void**)&Mean, g_mean);
    cudaGetSymbolAddress((void**)&Va,   g_va);
    cudaGetSymbolAddress((void**)&Vb,   g_vb);

    mean_part<<<dim3(4, NB), 256>>>(feat, noise);
    mean_final<<<NB, 256>>>();
    prep_kernel<<<dim3(NPG / 32, DIM / 32, NB), 256>>>(feat, noise,
        (__nv_bfloat16*)DTh, (__nv_bfloat16*)DTm);
    cov_mma<<<dim3(6, 1, NB), 256>>>(
        (const __nv_bfloat16*)DTh, (const __nv_bfloat16*)DTm, A);

    dim3 mv(8, NB);
    // v1 = 1.5*mean - 0.5*A@mean
    matvec_kernel<<<mv, 256>>>(A, Mean, Va, 1.5f, -0.5f, 0);

    // k = 0..2: M_{k+1} = f(M_k) = 2.25M - 1.5M^2 + 0.25M^3 ; v <- 1.5v - 0.5*M'v
    dim3 gg(6, 1, NB);
    float* Mcur = A;
    float* Mbuf[2] = {M0, M1};
    float* Vbuf[2] = {Va, Vb};
    int vc = 0;
    for (int k = 0; k < 3; ++k) {
        float* Mnext = Mbuf[k & 1];
        gemm_bf16<<<gg, 256>>>(Mcur, Mcur, X2, A, A, 0);      // X2 = M@M
        gemm_bf16<<<gg, 256>>>(X2, Mcur, Mnext, Mcur, X2, 1); // M' = f(M)
        matvec_kernel<<<mv, 256>>>(Mnext, Vbuf[vc], Vbuf[1 - vc], 1.5f, -0.5f, 0);
        vc ^= 1;
        Mcur = Mnext;
    }
    // fused tail: k=3 collapsed to matvecs + final projection, single launch
    tail_kernel<<<NB, 256>>>(Mcur, A, Vbuf[vc], out);
}

// round 16
// speedup vs baseline: 1.2820x; 1.0726x over previous
#include <cuda_runtime.h>
#include <cuda_bf16.h>
#include <math.h>
#include <stdint.h>

// Problem constants: feat [65536, 256], n_per_graph = 512 -> B = 128, d = 256.
#define NB   128
#define NPG  512
#define DIM  256
#define DD   (DIM*DIM)
#define BD   (NB*DD)
#define NOISE_RATE 0.01f

// Scratch (allocation-free rule: device globals)
__device__ float g_A[BD];      // A = cov/trace (fp32), preserved
__device__ float g_DTh[BD];    // bf16 [B][DIM][NPG]: diff^T hi
__device__ float g_DTm[BD];    // bf16 [B][DIM][NPG]: diff^T lo
__device__ float g_X2[BD];     // M^2 scratch
__device__ float g_M1[BD];     // M1
__device__ float g_M2[BD];     // M2
__device__ float g_M3[BD];     // M3
__device__ float g_mean[NB*DIM];
__device__ float g_norm[NB];
__device__ float g_psum[NB*4*DIM];
__device__ float g_psq[NB*4*DIM];

// ---------------------------------------------------------------------------
// helpers
// ---------------------------------------------------------------------------
__device__ __forceinline__ uint32_t smem_u32(const void* p) {
    uint32_t a;
    asm("{ .reg .u64 t; cvta.to.shared.u64 t, %1; cvt.u32.u64 %0, t; }" : "=r"(a) : "l"(p));
    return a;
}
__device__ __forceinline__ void ldm4(uint32_t* r, uint32_t a) {
    asm volatile("ldmatrix.sync.aligned.m8n8.x4.shared.b16 {%0,%1,%2,%3}, [%4];"
                 : "=r"(r[0]), "=r"(r[1]), "=r"(r[2]), "=r"(r[3]) : "r"(a));
}
__device__ __forceinline__ void mma16816(float* c, const uint32_t* a, const uint32_t* bq) {
    asm volatile("mma.sync.aligned.m16n8k16.row.col.f32.bf16.bf16.f32 "
                 "{%0,%1,%2,%3}, {%4,%5,%6,%7}, {%8,%9}, {%0,%1,%2,%3};"
                 : "+f"(c[0]), "+f"(c[1]), "+f"(c[2]), "+f"(c[3])
                 : "r"(a[0]), "r"(a[1]), "r"(a[2]), "r"(a[3]), "r"(bq[0]), "r"(bq[1]));
}
// bf16 2-term split of 4 floats -> packed h (2x u32) and m (2x u32)
__device__ __forceinline__ void split4(float4 v, uint32_t& h0, uint32_t& h1,
                                       uint32_t& q0, uint32_t& q1) {
    __nv_bfloat16 a = __float2bfloat16_rn(v.x);
    __nv_bfloat16 bb = __float2bfloat16_rn(v.y);
    __nv_bfloat16 c = __float2bfloat16_rn(v.z);
    __nv_bfloat16 d = __float2bfloat16_rn(v.w);
    __nv_bfloat162 hl; hl.x = a;  hl.y = bb;
    __nv_bfloat162 hh; hh.x = c;  hh.y = d;
    h0 = *(uint32_t*)&hl; h1 = *(uint32_t*)&hh;
    __nv_bfloat16 ma = __float2bfloat16_rn(v.x - __bfloat162float(a));
    __nv_bfloat16 mb = __float2bfloat16_rn(v.y - __bfloat162float(bb));
    __nv_bfloat16 mc = __float2bfloat16_rn(v.z - __bfloat162float(c));
    __nv_bfloat16 md = __float2bfloat16_rn(v.w - __bfloat162float(d));
    __nv_bfloat162 ml; ml.x = ma; ml.y = mb;
    __nv_bfloat162 mh; mh.x = mc; mh.y = md;
    q0 = *(uint32_t*)&ml; q1 = *(uint32_t*)&mh;
}

// symmetric-output tile map: 6 tiles cover the 2x4 (BM=128 x BN=64) grid of a
// 256x256 symmetric matrix. Tiles 2,3 are strictly upper -> mirror into lower.
__device__ __forceinline__ void sym_tile(int bx, int& mi, int& nj, int& mirror) {
    mi = (bx >= 4) ? 1 : 0;
    nj = (bx >= 4) ? (bx - 2) : bx;
    mirror = (bx == 2 || bx == 3) ? 1 : 0;
}

// ---------------------------------------------------------------------------
// mean stage 1: grid (4, NB), block 256: partial sum + sumsq over 128 nodes
// ---------------------------------------------------------------------------
__global__ void mean_part(const float* __restrict__ feat,
                          const float* __restrict__ noise) {
    int b = blockIdx.y, p = blockIdx.x, c = threadIdx.x;
    const float* F  = feat  + ((size_t)b * NPG + p * 128) * DIM + c;
    const float* Nz = noise + ((size_t)b * NPG + p * 128) * DIM + c;
    float s = 0.f, q = 0.f;
    #pragma unroll 8
    for (int n = 0; n < 128; ++n) {
        float v = F[(size_t)n * DIM] + NOISE_RATE * Nz[(size_t)n * DIM];
        s += v; q += v * v;
    }
    g_psum[(b * 4 + p) * DIM + c] = s;
    g_psq [(b * 4 + p) * DIM + c] = q;
}

// mean stage 2: grid NB, block 256: finalize mean + trace
__global__ void mean_final() {
    int b = blockIdx.x, c = threadIdx.x;
    float s = 0.f, q = 0.f;
    #pragma unroll
    for (int p = 0; p < 4; ++p) {
        s += g_psum[(b * 4 + p) * DIM + c];
        q += g_psq [(b * 4 + p) * DIM + c];
    }
    float m = s * (1.f / NPG);
    g_mean[b * DIM + c] = m;
    float t = q - (float)NPG * m * m;
    #pragma unroll
    for (int o = 16; o; o >>= 1) t += __shfl_xor_sync(0xffffffffu, t, o);
    __shared__ float sm[8];
    if ((c & 31) == 0) sm[c >> 5] = t;
    __syncthreads();
    if (c == 0) {
        float tot = 0.f;
        #pragma unroll
        for (int w = 0; w < 8; w++) tot += sm[w];
        g_norm[b] = tot * (1.f / (NPG - 1));
    }
}

// ---------------------------------------------------------------------------
// prep: diff^T split to bf16 (h, m), transposed to [b][dim][node].
// ---------------------------------------------------------------------------
__global__ void prep_kernel(const float* __restrict__ feat,
                            const float* __restrict__ noise,
                            __nv_bfloat16* __restrict__ DTh,
                            __nv_bfloat16* __restrict__ DTm) {
    int b = blockIdx.z;
    int n0 = blockIdx.x * 32, d0 = blockIdx.y * 32;
    __shared__ float t[32][33];
    __shared__ float mn[32];
    int tid = threadIdx.x;
    if (tid < 32) mn[tid] = g_mean[b * DIM + d0 + tid];
    __syncthreads();
    {
        int n = tid >> 3, dq = (tid & 7) * 4;
        size_t off = ((size_t)(b * NPG + n0 + n)) * DIM + d0 + dq;
        float4 f = *(const float4*)&feat[off];
        float4 z = *(const float4*)&noise[off];
        t[n][dq + 0] = f.x + NOISE_RATE * z.x - mn[dq + 0];
        t[n][dq + 1] = f.y + NOISE_RATE * z.y - mn[dq + 1];
        t[n][dq + 2] = f.z + NOISE_RATE * z.z - mn[dq + 2];
        t[n][dq + 3] = f.w + NOISE_RATE * z.w - mn[dq + 3];
    }
    __syncthreads();
    {
        int d = tid >> 3, nq = (tid & 7) * 4;
        float4 v = make_float4(t[nq + 0][d], t[nq + 1][d], t[nq + 2][d], t[nq + 3][d]);
        uint32_t h0, h1, m0, m1;
        split4(v, h0, h1, m0, m1);
        size_t off = ((size_t)(b * DIM + d0 + d)) * NPG + n0 + nq;
        *(uint2*)&DTh[off] = make_uint2(h0, h1);
        *(uint2*)&DTm[off] = make_uint2(m0, m1);
    }
}

// ---------------------------------------------------------------------------
// shared GEMM geometry (proven round-9)
// ---------------------------------------------------------------------------
#define BM 128
#define BN 64
#define RSTRIDE 80
#define OFF_AH 0
#define OFF_AM (BM * RSTRIDE)
#define OFF_BH (2 * BM * RSTRIDE)
#define OFF_BM (2 * BM * RSTRIDE + BN * RSTRIDE)
#define SMEM_GEMM (2 * BM * RSTRIDE + 2 * BN * RSTRIDE)

#define GEMM_FRAG_SETUP()                                                         \
    uint32_t aAd[2];                                                              \
    _Pragma("unroll")                                                             \
    for (int mt = 0; mt < 2; mt++)                                                \
        aAd[mt] = sb + OFF_AH + (uint32_t)(wm + mt * 16 + (lane & 15)) * RSTRIDE  \
                + ((lane >> 4) & 1) * 16;                                         \
    uint32_t bAd[2];                                                              \
    _Pragma("unroll")                                                             \
    for (int p = 0; p < 2; p++)                                                   \
        bAd[p] = sb + OFF_BH + (uint32_t)(wn + p * 16 + (lane & 7) + ((lane >> 4) & 1) * 8) * RSTRIDE \
               + ((lane >> 3) & 1) * 16;

#define GEMM_MAINLOOP_CHUNK()                                                     \
    _Pragma("unroll")                                                             \
    for (int kk = 0; kk < 2; kk++) {                                              \
        uint32_t ah[2][4], am[2][4];                                              \
        _Pragma("unroll")                                                         \
        for (int mt = 0; mt < 2; mt++) {                                          \
            ldm4(ah[mt], aAd[mt] + kk * 32);                                      \
            ldm4(am[mt], aAd[mt] + kk * 32 + (OFF_AM - OFF_AH));                  \
        }                                                                         \
        {                                                                         \
            uint32_t bb[2][4];                                                    \
            _Pragma("unroll")                                                     \
            for (int p = 0; p < 2; p++) ldm4(bb[p], bAd[p] + kk * 32);            \
            _Pragma("unroll")                                                     \
            for (int mt = 0; mt < 2; mt++)                                        \
                _Pragma("unroll")                                                 \
                for (int nt = 0; nt < 4; nt++) {                                  \
                    mma16816(acc[mt][nt], ah[mt], &bb[nt >> 1][(nt & 1) * 2]);    \
                    mma16816(acc[mt][nt], am[mt], &bb[nt >> 1][(nt & 1) * 2]);    \
                }                                                                 \
        }                                                                         \
        {                                                                         \
            uint32_t bb[2][4];                                                    \
            _Pragma("unroll")                                                     \
            for (int p = 0; p < 2; p++) ldm4(bb[p], bAd[p] + kk * 32 + (OFF_BM - OFF_BH)); \
            _Pragma("unroll")                                                     \
            for (int mt = 0; mt < 2; mt++)                                        \
                _Pragma("unroll")                                                 \
                for (int nt = 0; nt < 4; nt++)                                    \
                    mma16816(acc[mt][nt], ah[mt], &bb[nt >> 1][(nt & 1) * 2]);    \
        }                                                                         \
    }

// ---------------------------------------------------------------------------
// batched symmetric 256x256x256 GEMM via bf16 split (round-9 proven).
// mode 0: C = A@B.  mode 1: C = 2.25*P - 1.5*Q + 0.25*(A@B)
// ---------------------------------------------------------------------------
__global__ void __launch_bounds__(256, 2) gemm_bf16(const float* __restrict__ Ag,
                                                    const float* __restrict__ Bg,
                                                    float* __restrict__ Cg,
                                                    const float* __restrict__ Pg,
                                                    const float* __restrict__ Qg,
                                                    int mode) {
    __shared__ char smem[SMEM_GEMM];
    const uint32_t sb = smem_u32(smem);
    const int tid = threadIdx.x, lane = tid & 31, wid = tid >> 5;
    const int b = blockIdx.z;
    int mi, nj, mirror;
    sym_tile(blockIdx.x, mi, nj, mirror);
    const int m0 = mi * BM, n0 = nj * BN;
    const int wm = (wid & 3) * 32, wn = (wid >> 2) * 32;
    const float* A  = Ag + (size_t)b * DD;
    const float* Bm = Bg + (size_t)b * DD;

    const int srow = tid >> 3, skq = tid & 7;
    const float* gA = A  + (size_t)(m0 + srow) * DIM + skq * 4;
    const float* gB = Bm + (size_t)(n0 + srow) * DIM + skq * 4;
    const uint32_t stOff = (uint32_t)srow * RSTRIDE + skq * 8;

    GEMM_FRAG_SETUP();

    float acc[2][4][4];
    #pragma unroll
    for (int mt = 0; mt < 2; mt++)
        #pragma unroll
        for (int nt = 0; nt < 4; nt++)
            #pragma unroll
            for (int k = 0; k < 4; k++) acc[mt][nt][k] = 0.f;

    float4 pa[4], pb[2];
    #pragma unroll
    for (int p = 0; p < 4; p++) pa[p] = *(const float4*)(gA + (size_t)p * 32 * DIM);
    #pragma unroll
    for (int p = 0; p < 2; p++) pb[p] = *(const float4*)(gB + (size_t)p * 32 * DIM);

    for (int kc = 0; kc < 8; ++kc) {
        #pragma unroll
        for (int p = 0; p < 4; p++) {
            uint32_t h0, h1, q0, q1;
            split4(pa[p], h0, h1, q0, q1);
            uint32_t ad = stOff + p * 32 * RSTRIDE;
            *((uint2*)(smem + ad + OFF_AH)) = make_uint2(h0, h1);
            *((uint2*)(smem + ad + OFF_AM)) = make_uint2(q0, q1);
        }
        #pragma unroll
        for (int p = 0; p < 2; p++) {
            uint32_t h0, h1, q0, q1;
            split4(pb[p], h0, h1, q0, q1);
            uint32_t ad = stOff + p * 32 * RSTRIDE;
            *((uint2*)(smem + ad + OFF_BH)) = make_uint2(h0, h1);
            *((uint2*)(smem + ad + OFF_BM)) = make_uint2(q0, q1);
        }
        __syncthreads();
        if (kc < 7) {
            #pragma unroll
            for (int p = 0; p < 4; p++) pa[p] = *(const float4*)(gA + (size_t)p * 32 * DIM + (kc + 1) * 32);
            #pragma unroll
            for (int p = 0; p < 2; p++) pb[p] = *(const float4*)(gB + (size_t)p * 32 * DIM + (kc + 1) * 32);
        }
        GEMM_MAINLOOP_CHUNK();
        __syncthreads();
    }

    float* C = Cg + (size_t)b * DD;
    const float* P = Pg + (size_t)b * DD;
    const float* Q = Qg + (size_t)b * DD;
    int rr = m0 + wm + (lane >> 2);
    int cc = n0 + wn + (lane & 3) * 2;
    #pragma unroll
    for (int mt = 0; mt < 2; mt++) {
        #pragma unroll
        for (int nt = 0; nt < 4; nt++) {
            int r = rr + mt * 16, c = cc + nt * 8;
            float v0 = acc[mt][nt][0], v1 = acc[mt][nt][1];
            float v2 = acc[mt][nt][2], v3 = acc[mt][nt][3];
            if (mode == 1) {
                float2 p0 = *(const float2*)&P[(size_t)r * DIM + c];
                float2 p1 = *(const float2*)&P[(size_t)(r + 8) * DIM + c];
                float2 q0 = *(const float2*)&Q[(size_t)r * DIM + c];
                float2 q1 = *(const float2*)&Q[(size_t)(r + 8) * DIM + c];
                v0 = 2.25f * p0.x - 1.5f * q0.x + 0.25f * v0;
                v1 = 2.25f * p0.y - 1.5f * q0.y + 0.25f * v1;
                v2 = 2.25f * p1.x - 1.5f * q1.x + 0.25f * v2;
                v3 = 2.25f * p1.y - 1.5f * q1.y + 0.25f * v3;
            }
            *(float2*)&C[(size_t)r * DIM + c]       = make_float2(v0, v1);
            *(float2*)&C[(size_t)(r + 8) * DIM + c] = make_float2(v2, v3);
            if (mirror) {
                C[(size_t)(c + 0) * DIM + r]     = v0;
                C[(size_t)(c + 1) * DIM + r]     = v1;
                C[(size_t)(c + 0) * DIM + r + 8] = v2;
                C[(size_t)(c + 1) * DIM + r + 8] = v3;
            }
        }
    }
}

// ---------------------------------------------------------------------------
// covariance GEMM: A = (diff^T @ diff) / ((N-1)*trace), K = 512. Symmetric.
// ---------------------------------------------------------------------------
__global__ void __launch_bounds__(256, 2) cov_mma(const __nv_bfloat16* __restrict__ DTh,
                                                  const __nv_bfloat16* __restrict__ DTm,
                                                  float* __restrict__ Cg) {
    __shared__ char smem[SMEM_GEMM];
    const uint32_t sb = smem_u32(smem);
    const int tid = threadIdx.x, lane = tid & 31, wid = tid >> 5;
    const int b = blockIdx.z;
    int mi, nj, mirror;
    sym_tile(blockIdx.x, mi, nj, mirror);
    const int m0 = mi * BM, n0 = nj * BN;
    const int wm = (wid & 3) * 32, wn = (wid >> 2) * 32;

    const int lrow = tid >> 2, lq = tid & 3;
    const __nv_bfloat16* baseH = DTh + (size_t)b * DIM * NPG;
    const __nv_bfloat16* baseM = DTm + (size_t)b * DIM * NPG;

    GEMM_FRAG_SETUP();

    float acc[2][4][4];
    #pragma unroll
    for (int mt = 0; mt < 2; mt++)
        #pragma unroll
        for (int nt = 0; nt < 4; nt++)
            #pragma unroll
            for (int k = 0; k < 4; k++) acc[mt][nt][k] = 0.f;

    uint4 pAh[2], pAm[2], pBh, pBm;
    {
        size_t a0 = (size_t)(m0 + lrow) * NPG + lq * 8;
        size_t a1 = (size_t)(m0 + 64 + lrow) * NPG + lq * 8;
        size_t b0 = (size_t)(n0 + lrow) * NPG + lq * 8;
        pAh[0] = *(const uint4*)(baseH + a0); pAm[0] = *(const uint4*)(baseM + a0);
        pAh[1] = *(const uint4*)(baseH + a1); pAm[1] = *(const uint4*)(baseM + a1);
        pBh    = *(const uint4*)(baseH + b0); pBm    = *(const uint4*)(baseM + b0);
    }

    for (int kc = 0; kc < 16; ++kc) {
        {
            uint32_t ad0 = (uint32_t)lrow * RSTRIDE + lq * 16;
            uint32_t ad1 = (uint32_t)(64 + lrow) * RSTRIDE + lq * 16;
            *((uint4*)(smem + ad0 + OFF_AH)) = pAh[0];
            *((uint4*)(smem + ad0 + OFF_AM)) = pAm[0];
            *((uint4*)(smem + ad1 + OFF_AH)) = pAh[1];
            *((uint4*)(smem + ad1 + OFF_AM)) = pAm[1];
            *((uint4*)(smem + ad0 + OFF_BH)) = pBh;
            *((uint4*)(smem + ad0 + OFF_BM)) = pBm;
        }
        __syncthreads();
        if (kc < 15) {
            size_t ko = (size_t)(kc + 1) * 32 + lq * 8;
            size_t a0 = (size_t)(m0 + lrow) * NPG + ko;
            size_t a1 = (size_t)(m0 + 64 + lrow) * NPG + ko;
            size_t b0 = (size_t)(n0 + lrow) * NPG + ko;
            pAh[0] = *(const uint4*)(baseH + a0); pAm[0] = *(const uint4*)(baseM + a0);
            pAh[1] = *(const uint4*)(baseH + a1); pAm[1] = *(const uint4*)(baseM + a1);
            pBh    = *(const uint4*)(baseH + b0); pBm    = *(const uint4*)(baseM + b0);
        }
        GEMM_MAINLOOP_CHUNK();
        __syncthreads();
    }

    float* C = Cg + (size_t)b * DD;
    const float sc = 1.f / ((NPG - 1) * g_norm[b]);
    int rr = m0 + wm + (lane >> 2);
    int cc = n0 + wn + (lane & 3) * 2;
    #pragma unroll
    for (int mt = 0; mt < 2; mt++) {
        #pragma unroll
        for (int nt = 0; nt < 4; nt++) {
            int r = rr + mt * 16, c = cc + nt * 8;
            float v0 = acc[mt][nt][0] * sc, v1 = acc[mt][nt][1] * sc;
            float v2 = acc[mt][nt][2] * sc, v3 = acc[mt][nt][3] * sc;
            *(float2*)&C[(size_t)r * DIM + c]       = make_float2(v0, v1);
            *(float2*)&C[(size_t)(r + 8) * DIM + c] = make_float2(v2, v3);
            if (mirror) {
                C[(size_t)(c + 0) * DIM + r]     = v0;
                C[(size_t)(c + 1) * DIM + r]     = v1;
                C[(size_t)(c + 0) * DIM + r + 8] = v2;
                C[(size_t)(c + 1) * DIM + r + 8] = v3;
            }
        }
    }
}

// ---------------------------------------------------------------------------
// block-local matvec for 512 threads: ws = Mb @ xs (256x256).
// 16 warps, warp handles 4 rows/pass (8 lanes per row), 4 passes.
// ---------------------------------------------------------------------------
__device__ __forceinline__ void block_matvec512(const float* __restrict__ Mb,
                                                const float* __restrict__ xs,
                                                float* __restrict__ ws, int tid) {
    int warp = tid >> 5, lane = tid & 31;
    #pragma unroll
    for (int pass = 0; pass < 4; ++pass) {
        int r = pass * 64 + warp * 4 + (lane >> 3);
        int c0 = (lane & 7) * 32;
        const float* Mr = Mb + (size_t)r * DIM + c0;
        float s = 0.f;
        #pragma unroll
        for (int c = 0; c < 32; c += 4) {
            float4 mv = *(const float4*)(Mr + c);
            s += mv.x * xs[c0 + c] + mv.y * xs[c0 + c + 1]
               + mv.z * xs[c0 + c + 2] + mv.w * xs[c0 + c + 3];
        }
        #pragma unroll
        for (int o = 4; o; o >>= 1) s += __shfl_xor_sync(0xffffffffu, s, o);
        if ((lane & 7) == 0) ws[r] = s;
    }
}

// ---------------------------------------------------------------------------
// fused vector pipeline: one 512-thread block per batch.
// v = mean; for M in {A, M1, M2, M3}: v = 1.5v - 0.5*Mv
// then w1 = M3 v; w2 = M3 w1; w3 = M3 w2;
// x5 = 1.5v - 1.125w1 + 0.75w2 - 0.125w3;  out = sqrt(norm) * A @ x5
// ---------------------------------------------------------------------------
__global__ void __launch_bounds__(512) tail_kernel(const float* __restrict__ A,
                                                   const float* __restrict__ M1,
                                                   const float* __restrict__ M2,
                                                   const float* __restrict__ M3,
                                                   float* __restrict__ out) {
    int b = blockIdx.x, tid = threadIdx.x;
    __shared__ float v[DIM], w[DIM], w1[DIM], w2[DIM];
    const float* Ab  = A  + (size_t)b * DD;
    const float* M1b = M1 + (size_t)b * DD;
    const float* M2b = M2 + (size_t)b * DD;
    const float* M3b = M3 + (size_t)b * DD;
    if (tid < DIM) v[tid] = g_mean[b * DIM + tid];
    __syncthreads();
    // four NS vector updates
    block_matvec512(Ab,  v, w, tid); __syncthreads();
    if (tid < DIM) v[tid] = 1.5f * v[tid] - 0.5f * w[tid];
    __syncthreads();
    block_matvec512(M1b, v, w, tid); __syncthreads();
    if (tid < DIM) v[tid] = 1.5f * v[tid] - 0.5f * w[tid];
    __syncthreads();
    block_matvec512(M2b, v, w, tid); __syncthreads();
    if (tid < DIM) v[tid] = 1.5f * v[tid] - 0.5f * w[tid];
    __syncthreads();
    block_matvec512(M3b, v, w, tid); __syncthreads();
    if (tid < DIM) v[tid] = 1.5f * v[tid] - 0.5f * w[tid];
    __syncthreads();
    // w-chain with M3
    block_matvec512(M3b, v,  w1, tid); __syncthreads();
    block_matvec512(M3b, w1, w2, tid); __syncthreads();
    block_matvec512(M3b, w2, w,  tid); __syncthreads();
    if (tid < DIM)
        v[tid] = 1.5f * v[tid] - 1.125f * w1[tid] + 0.75f * w2[tid] - 0.125f * w[tid];
    __syncthreads();
    block_matvec512(Ab, v, w, tid); __syncthreads();
    if (tid < DIM) out[b * DIM + tid] = sqrtf(g_norm[b]) * w[tid];
}

// ---------------------------------------------------------------------------
extern "C" void kernel_launch(void* const* d_in, const int* in_sizes, int n_in,
                              void* d_out, int out_size) {
    const float* feat  = (const float*)d_in[0];
    const float* noise = (const float*)d_in[1];
    float* out = (float*)d_out;

    float *A, *DTh, *DTm, *X2, *M1, *M2, *M3;
    cudaGetSymbolAddress((void**)&A,    g_A);
    cudaGetSymbolAddress((void**)&DTh,  g_DTh);
    cudaGetSymbolAddress((void**)&DTm,  g_DTm);
    cudaGetSymbolAddress((void**)&X2,   g_X2);
    cudaGetSymbolAddress((void**)&M1,   g_M1);
    cudaGetSymbolAddress((void**)&M2,   g_M2);
    cudaGetSymbolAddress((void**)&M3,   g_M3);

    mean_part<<<dim3(4, NB), 256>>>(feat, noise);
    mean_final<<<NB, 256>>>();
    prep_kernel<<<dim3(NPG / 32, DIM / 32, NB), 256>>>(feat, noise,
        (__nv_bfloat16*)DTh, (__nv_bfloat16*)DTm);
    cov_mma<<<dim3(6, 1, NB), 256>>>(
        (const __nv_bfloat16*)DTh, (const __nv_bfloat16*)DTm, A);

    // 3 NS matrix iterations, back-to-back (no interleaved vector work):
    // M1 = f(A), M2 = f(M1), M3 = f(M2);  f(M) = 2.25M - 1.5M^2 + 0.25M^3
    dim3 gg(6, 1, NB);
    gemm_bf16<<<gg, 256>>>(A,  A,  X2, A,  A,  0);
    gemm_bf16<<<gg, 256>>>(X2, A,  M1, A,  X2, 1);
    gemm_bf16<<<gg, 256>>>(M1, M1, X2, A,  A,  0);
    gemm_bf16<<<gg, 256>>>(X2, M1, M2, M1, X2, 1);
    gemm_bf16<<<gg, 256>>>(M2, M2, X2, A,  A,  0);
    gemm_bf16<<<gg, 256>>>(X2, M2, M3, M2, X2, 1);

    // all vector work + final projection in ONE launch
    tail_kernel<<<NB, 512>>>(A, M1, M2, M3, out);
}

// round 17
// speedup vs baseline: 1.5291x; 1.1928x over previous
#include <cuda_runtime.h>
#include <cuda_bf16.h>
#include <math.h>
#include <stdint.h>

// Problem constants: feat [65536, 256], n_per_graph = 512 -> B = 128, d = 256.
#define NB   128
#define NPG  512
#define DIM  256
#define DD   (DIM*DIM)
#define BD   (NB*DD)
#define NOISE_RATE 0.01f

// Scratch (allocation-free rule: device globals)
__device__ float g_A[BD];      // A = cov/trace (fp32), preserved
__device__ float g_DTh[BD];    // bf16 [B][DIM][NPG]: diff^T hi
__device__ float g_DTm[BD];    // bf16 [B][DIM][NPG]: diff^T lo
__device__ float g_X2[BD];     // M^2 scratch
__device__ float g_M1[BD];     // M1
__device__ float g_M2[BD];     // M2
__device__ float g_mean[NB*DIM];
__device__ float g_norm[NB];
__device__ float g_psum[NB*4*DIM];
__device__ float g_psq[NB*4*DIM];

// ---------------------------------------------------------------------------
// helpers
// ---------------------------------------------------------------------------
__device__ __forceinline__ uint32_t smem_u32(const void* p) {
    uint32_t a;
    asm("{ .reg .u64 t; cvta.to.shared.u64 t, %1; cvt.u32.u64 %0, t; }" : "=r"(a) : "l"(p));
    return a;
}
__device__ __forceinline__ void ldm4(uint32_t* r, uint32_t a) {
    asm volatile("ldmatrix.sync.aligned.m8n8.x4.shared.b16 {%0,%1,%2,%3}, [%4];"
                 : "=r"(r[0]), "=r"(r[1]), "=r"(r[2]), "=r"(r[3]) : "r"(a));
}
__device__ __forceinline__ void mma16816(float* c, const uint32_t* a, const uint32_t* bq) {
    asm volatile("mma.sync.aligned.m16n8k16.row.col.f32.bf16.bf16.f32 "
                 "{%0,%1,%2,%3}, {%4,%5,%6,%7}, {%8,%9}, {%0,%1,%2,%3};"
                 : "+f"(c[0]), "+f"(c[1]), "+f"(c[2]), "+f"(c[3])
                 : "r"(a[0]), "r"(a[1]), "r"(a[2]), "r"(a[3]), "r"(bq[0]), "r"(bq[1]));
}
// bf16 2-term split of 4 floats -> packed h (2x u32) and m (2x u32)
__device__ __forceinline__ void split4(float4 v, uint32_t& h0, uint32_t& h1,
                                       uint32_t& q0, uint32_t& q1) {
    __nv_bfloat16 a = __float2bfloat16_rn(v.x);
    __nv_bfloat16 bb = __float2bfloat16_rn(v.y);
    __nv_bfloat16 c = __float2bfloat16_rn(v.z);
    __nv_bfloat16 d = __float2bfloat16_rn(v.w);
    __nv_bfloat162 hl; hl.x = a;  hl.y = bb;
    __nv_bfloat162 hh; hh.x = c;  hh.y = d;
    h0 = *(uint32_t*)&hl; h1 = *(uint32_t*)&hh;
    __nv_bfloat16 ma = __float2bfloat16_rn(v.x - __bfloat162float(a));
    __nv_bfloat16 mb = __float2bfloat16_rn(v.y - __bfloat162float(bb));
    __nv_bfloat16 mc = __float2bfloat16_rn(v.z - __bfloat162float(c));
    __nv_bfloat16 md = __float2bfloat16_rn(v.w - __bfloat162float(d));
    __nv_bfloat162 ml; ml.x = ma; ml.y = mb;
    __nv_bfloat162 mh; mh.x = mc; mh.y = md;
    q0 = *(uint32_t*)&ml; q1 = *(uint32_t*)&mh;
}

// symmetric-output tile map: 6 tiles cover the 2x4 (BM=128 x BN=64) grid of a
// 256x256 symmetric matrix. Tiles 2,3 are strictly upper -> mirror into lower.
__device__ __forceinline__ void sym_tile(int bx, int& mi, int& nj, int& mirror) {
    mi = (bx >= 4) ? 1 : 0;
    nj = (bx >= 4) ? (bx - 2) : bx;
    mirror = (bx == 2 || bx == 3) ? 1 : 0;
}

// ---------------------------------------------------------------------------
// mean stage 1: grid (4, NB), block 256: partial sum + sumsq over 128 nodes
// ---------------------------------------------------------------------------
__global__ void mean_part(const float* __restrict__ feat,
                          const float* __restrict__ noise) {
    int b = blockIdx.y, p = blockIdx.x, c = threadIdx.x;
    const float* F  = feat  + ((size_t)b * NPG + p * 128) * DIM + c;
    const float* Nz = noise + ((size_t)b * NPG + p * 128) * DIM + c;
    float s = 0.f, q = 0.f;
    #pragma unroll 8
    for (int n = 0; n < 128; ++n) {
        float v = F[(size_t)n * DIM] + NOISE_RATE * Nz[(size_t)n * DIM];
        s += v; q += v * v;
    }
    g_psum[(b * 4 + p) * DIM + c] = s;
    g_psq [(b * 4 + p) * DIM + c] = q;
}

// mean stage 2: grid NB, block 256: finalize mean + trace
__global__ void mean_final() {
    int b = blockIdx.x, c = threadIdx.x;
    float s = 0.f, q = 0.f;
    #pragma unroll
    for (int p = 0; p < 4; ++p) {
        s += g_psum[(b * 4 + p) * DIM + c];
        q += g_psq [(b * 4 + p) * DIM + c];
    }
    float m = s * (1.f / NPG);
    g_mean[b * DIM + c] = m;
    float t = q - (float)NPG * m * m;
    #pragma unroll
    for (int o = 16; o; o >>= 1) t += __shfl_xor_sync(0xffffffffu, t, o);
    __shared__ float sm[8];
    if ((c & 31) == 0) sm[c >> 5] = t;
    __syncthreads();
    if (c == 0) {
        float tot = 0.f;
        #pragma unroll
        for (int w = 0; w < 8; w++) tot += sm[w];
        g_norm[b] = tot * (1.f / (NPG - 1));
    }
}

// ---------------------------------------------------------------------------
// prep: diff^T split to bf16 (h, m), transposed to [b][dim][node].
// ---------------------------------------------------------------------------
__global__ void prep_kernel(const float* __restrict__ feat,
                            const float* __restrict__ noise,
                            __nv_bfloat16* __restrict__ DTh,
                            __nv_bfloat16* __restrict__ DTm) {
    int b = blockIdx.z;
    int n0 = blockIdx.x * 32, d0 = blockIdx.y * 32;
    __shared__ float t[32][33];
    __shared__ float mn[32];
    int tid = threadIdx.x;
    if (tid < 32) mn[tid] = g_mean[b * DIM + d0 + tid];
    __syncthreads();
    {
        int n = tid >> 3, dq = (tid & 7) * 4;
        size_t off = ((size_t)(b * NPG + n0 + n)) * DIM + d0 + dq;
        float4 f = *(const float4*)&feat[off];
        float4 z = *(const float4*)&noise[off];
        t[n][dq + 0] = f.x + NOISE_RATE * z.x - mn[dq + 0];
        t[n][dq + 1] = f.y + NOISE_RATE * z.y - mn[dq + 1];
        t[n][dq + 2] = f.z + NOISE_RATE * z.z - mn[dq + 2];
        t[n][dq + 3] = f.w + NOISE_RATE * z.w - mn[dq + 3];
    }
    __syncthreads();
    {
        int d = tid >> 3, nq = (tid & 7) * 4;
        float4 v = make_float4(t[nq + 0][d], t[nq + 1][d], t[nq + 2][d], t[nq + 3][d]);
        uint32_t h0, h1, m0, m1;
        split4(v, h0, h1, m0, m1);
        size_t off = ((size_t)(b * DIM + d0 + d)) * NPG + n0 + nq;
        *(uint2*)&DTh[off] = make_uint2(h0, h1);
        *(uint2*)&DTm[off] = make_uint2(m0, m1);
    }
}

// ---------------------------------------------------------------------------
// shared GEMM geometry (proven round-9)
// ---------------------------------------------------------------------------
#define BM 128
#define BN 64
#define RSTRIDE 80
#define OFF_AH 0
#define OFF_AM (BM * RSTRIDE)
#define OFF_BH (2 * BM * RSTRIDE)
#define OFF_BM (2 * BM * RSTRIDE + BN * RSTRIDE)
#define SMEM_GEMM (2 * BM * RSTRIDE + 2 * BN * RSTRIDE)

#define GEMM_FRAG_SETUP()                                                         \
    uint32_t aAd[2];                                                              \
    _Pragma("unroll")                                                             \
    for (int mt = 0; mt < 2; mt++)                                                \
        aAd[mt] = sb + OFF_AH + (uint32_t)(wm + mt * 16 + (lane & 15)) * RSTRIDE  \
                + ((lane >> 4) & 1) * 16;                                         \
    uint32_t bAd[2];                                                              \
    _Pragma("unroll")                                                             \
    for (int p = 0; p < 2; p++)                                                   \
        bAd[p] = sb + OFF_BH + (uint32_t)(wn + p * 16 + (lane & 7) + ((lane >> 4) & 1) * 8) * RSTRIDE \
               + ((lane >> 3) & 1) * 16;

#define GEMM_MAINLOOP_CHUNK()                                                     \
    _Pragma("unroll")                                                             \
    for (int kk = 0; kk < 2; kk++) {                                              \
        uint32_t ah[2][4], am[2][4];                                              \
        _Pragma("unroll")                                                         \
        for (int mt = 0; mt < 2; mt++) {                                          \
            ldm4(ah[mt], aAd[mt] + kk * 32);                                      \
            ldm4(am[mt], aAd[mt] + kk * 32 + (OFF_AM - OFF_AH));                  \
        }                                                                         \
        {                                                                         \
            uint32_t bb[2][4];                                                    \
            _Pragma("unroll")                                                     \
            for (int p = 0; p < 2; p++) ldm4(bb[p], bAd[p] + kk * 32);            \
            _Pragma("unroll")                                                     \
            for (int mt = 0; mt < 2; mt++)                                        \
                _Pragma("unroll")                                                 \
                for (int nt = 0; nt < 4; nt++) {                                  \
                    mma16816(acc[mt][nt], ah[mt], &bb[nt >> 1][(nt & 1) * 2]);    \
                    mma16816(acc[mt][nt], am[mt], &bb[nt >> 1][(nt & 1) * 2]);    \
                }                                                                 \
        }                                                                         \
        {                                                                         \
            uint32_t bb[2][4];                                                    \
            _Pragma("unroll")                                                     \
            for (int p = 0; p < 2; p++) ldm4(bb[p], bAd[p] + kk * 32 + (OFF_BM - OFF_BH)); \
            _Pragma("unroll")                                                     \
            for (int mt = 0; mt < 2; mt++)                                        \
                _Pragma("unroll")                                                 \
                for (int nt = 0; nt < 4; nt++)                                    \
                    mma16816(acc[mt][nt], ah[mt], &bb[nt >> 1][(nt & 1) * 2]);    \
        }                                                                         \
    }

// ---------------------------------------------------------------------------
// batched symmetric 256x256x256 GEMM via bf16 split (round-9 proven).
// mode 0: C = A@B.  mode 1: C = 2.25*P - 1.5*Q + 0.25*(A@B)
// ---------------------------------------------------------------------------
__global__ void __launch_bounds__(256, 2) gemm_bf16(const float* __restrict__ Ag,
                                                    const float* __restrict__ Bg,
                                                    float* __restrict__ Cg,
                                                    const float* __restrict__ Pg,
                                                    const float* __restrict__ Qg,
                                                    int mode) {
    __shared__ char smem[SMEM_GEMM];
    const uint32_t sb = smem_u32(smem);
    const int tid = threadIdx.x, lane = tid & 31, wid = tid >> 5;
    const int b = blockIdx.z;
    int mi, nj, mirror;
    sym_tile(blockIdx.x, mi, nj, mirror);
    const int m0 = mi * BM, n0 = nj * BN;
    const int wm = (wid & 3) * 32, wn = (wid >> 2) * 32;
    const float* A  = Ag + (size_t)b * DD;
    const float* Bm = Bg + (size_t)b * DD;

    const int srow = tid >> 3, skq = tid & 7;
    const float* gA = A  + (size_t)(m0 + srow) * DIM + skq * 4;
    const float* gB = Bm + (size_t)(n0 + srow) * DIM + skq * 4;
    const uint32_t stOff = (uint32_t)srow * RSTRIDE + skq * 8;

    GEMM_FRAG_SETUP();

    float acc[2][4][4];
    #pragma unroll
    for (int mt = 0; mt < 2; mt++)
        #pragma unroll
        for (int nt = 0; nt < 4; nt++)
            #pragma unroll
            for (int k = 0; k < 4; k++) acc[mt][nt][k] = 0.f;

    float4 pa[4], pb[2];
    #pragma unroll
    for (int p = 0; p < 4; p++) pa[p] = *(const float4*)(gA + (size_t)p * 32 * DIM);
    #pragma unroll
    for (int p = 0; p < 2; p++) pb[p] = *(const float4*)(gB + (size_t)p * 32 * DIM);

    for (int kc = 0; kc < 8; ++kc) {
        #pragma unroll
        for (int p = 0; p < 4; p++) {
            uint32_t h0, h1, q0, q1;
            split4(pa[p], h0, h1, q0, q1);
            uint32_t ad = stOff + p * 32 * RSTRIDE;
            *((uint2*)(smem + ad + OFF_AH)) = make_uint2(h0, h1);
            *((uint2*)(smem + ad + OFF_AM)) = make_uint2(q0, q1);
        }
        #pragma unroll
        for (int p = 0; p < 2; p++) {
            uint32_t h0, h1, q0, q1;
            split4(pb[p], h0, h1, q0, q1);
            uint32_t ad = stOff + p * 32 * RSTRIDE;
            *((uint2*)(smem + ad + OFF_BH)) = make_uint2(h0, h1);
            *((uint2*)(smem + ad + OFF_BM)) = make_uint2(q0, q1);
        }
        __syncthreads();
        if (kc < 7) {
            #pragma unroll
            for (int p = 0; p < 4; p++) pa[p] = *(const float4*)(gA + (size_t)p * 32 * DIM + (kc + 1) * 32);
            #pragma unroll
            for (int p = 0; p < 2; p++) pb[p] = *(const float4*)(gB + (size_t)p * 32 * DIM + (kc + 1) * 32);
        }
        GEMM_MAINLOOP_CHUNK();
        __syncthreads();
    }

    float* C = Cg + (size_t)b * DD;
    const float* P = Pg + (size_t)b * DD;
    const float* Q = Qg + (size_t)b * DD;
    int rr = m0 + wm + (lane >> 2);
    int cc = n0 + wn + (lane & 3) * 2;
    #pragma unroll
    for (int mt = 0; mt < 2; mt++) {
        #pragma unroll
        for (int nt = 0; nt < 4; nt++) {
            int r = rr + mt * 16, c = cc + nt * 8;
            float v0 = acc[mt][nt][0], v1 = acc[mt][nt][1];
            float v2 = acc[mt][nt][2], v3 = acc[mt][nt][3];
            if (mode == 1) {
                float2 p0 = *(const float2*)&P[(size_t)r * DIM + c];
                float2 p1 = *(const float2*)&P[(size_t)(r + 8) * DIM + c];
                float2 q0 = *(const float2*)&Q[(size_t)r * DIM + c];
                float2 q1 = *(const float2*)&Q[(size_t)(r + 8) * DIM + c];
                v0 = 2.25f * p0.x - 1.5f * q0.x + 0.25f * v0;
                v1 = 2.25f * p0.y - 1.5f * q0.y + 0.25f * v1;
                v2 = 2.25f * p1.x - 1.5f * q1.x + 0.25f * v2;
                v3 = 2.25f * p1.y - 1.5f * q1.y + 0.25f * v3;
            }
            *(float2*)&C[(size_t)r * DIM + c]       = make_float2(v0, v1);
            *(float2*)&C[(size_t)(r + 8) * DIM + c] = make_float2(v2, v3);
            if (mirror) {
                C[(size_t)(c + 0) * DIM + r]     = v0;
                C[(size_t)(c + 1) * DIM + r]     = v1;
                C[(size_t)(c + 0) * DIM + r + 8] = v2;
                C[(size_t)(c + 1) * DIM + r + 8] = v3;
            }
        }
    }
}

// ---------------------------------------------------------------------------
// covariance GEMM: A = (diff^T @ diff) / ((N-1)*trace), K = 512. Symmetric.
// ---------------------------------------------------------------------------
__global__ void __launch_bounds__(256, 2) cov_mma(const __nv_bfloat16* __restrict__ DTh,
                                                  const __nv_bfloat16* __restrict__ DTm,
                                                  float* __restrict__ Cg) {
    __shared__ char smem[SMEM_GEMM];
    const uint32_t sb = smem_u32(smem);
    const int tid = threadIdx.x, lane = tid & 31, wid = tid >> 5;
    const int b = blockIdx.z;
    int mi, nj, mirror;
    sym_tile(blockIdx.x, mi, nj, mirror);
    const int m0 = mi * BM, n0 = nj * BN;
    const int wm = (wid & 3) * 32, wn = (wid >> 2) * 32;

    const int lrow = tid >> 2, lq = tid & 3;
    const __nv_bfloat16* baseH = DTh + (size_t)b * DIM * NPG;
    const __nv_bfloat16* baseM = DTm + (size_t)b * DIM * NPG;

    GEMM_FRAG_SETUP();

    float acc[2][4][4];
    #pragma unroll
    for (int mt = 0; mt < 2; mt++)
        #pragma unroll
        for (int nt = 0; nt < 4; nt++)
            #pragma unroll
            for (int k = 0; k < 4; k++) acc[mt][nt][k] = 0.f;

    uint4 pAh[2], pAm[2], pBh, pBm;
    {
        size_t a0 = (size_t)(m0 + lrow) * NPG + lq * 8;
        size_t a1 = (size_t)(m0 + 64 + lrow) * NPG + lq * 8;
        size_t b0 = (size_t)(n0 + lrow) * NPG + lq * 8;
        pAh[0] = *(const uint4*)(baseH + a0); pAm[0] = *(const uint4*)(baseM + a0);
        pAh[1] = *(const uint4*)(baseH + a1); pAm[1] = *(const uint4*)(baseM + a1);
        pBh    = *(const uint4*)(baseH + b0); pBm    = *(const uint4*)(baseM + b0);
    }

    for (int kc = 0; kc < 16; ++kc) {
        {
            uint32_t ad0 = (uint32_t)lrow * RSTRIDE + lq * 16;
            uint32_t ad1 = (uint32_t)(64 + lrow) * RSTRIDE + lq * 16;
            *((uint4*)(smem + ad0 + OFF_AH)) = pAh[0];
            *((uint4*)(smem + ad0 + OFF_AM)) = pAm[0];
            *((uint4*)(smem + ad1 + OFF_AH)) = pAh[1];
            *((uint4*)(smem + ad1 + OFF_AM)) = pAm[1];
            *((uint4*)(smem + ad0 + OFF_BH)) = pBh;
            *((uint4*)(smem + ad0 + OFF_BM)) = pBm;
        }
        __syncthreads();
        if (kc < 15) {
            size_t ko = (size_t)(kc + 1) * 32 + lq * 8;
            size_t a0 = (size_t)(m0 + lrow) * NPG + ko;
            size_t a1 = (size_t)(m0 + 64 + lrow) * NPG + ko;
            size_t b0 = (size_t)(n0 + lrow) * NPG + ko;
            pAh[0] = *(const uint4*)(baseH + a0); pAm[0] = *(const uint4*)(baseM + a0);
            pAh[1] = *(const uint4*)(baseH + a1); pAm[1] = *(const uint4*)(baseM + a1);
            pBh    = *(const uint4*)(baseH + b0); pBm    = *(const uint4*)(baseM + b0);
        }
        GEMM_MAINLOOP_CHUNK();
        __syncthreads();
    }

    float* C = Cg + (size_t)b * DD;
    const float sc = 1.f / ((NPG - 1) * g_norm[b]);
    int rr = m0 + wm + (lane >> 2);
    int cc = n0 + wn + (lane & 3) * 2;
    #pragma unroll
    for (int mt = 0; mt < 2; mt++) {
        #pragma unroll
        for (int nt = 0; nt < 4; nt++) {
            int r = rr + mt * 16, c = cc + nt * 8;
            float v0 = acc[mt][nt][0] * sc, v1 = acc[mt][nt][1] * sc;
            float v2 = acc[mt][nt][2] * sc, v3 = acc[mt][nt][3] * sc;
            *(float2*)&C[(size_t)r * DIM + c]       = make_float2(v0, v1);
            *(float2*)&C[(size_t)(r + 8) * DIM + c] = make_float2(v2, v3);
            if (mirror) {
                C[(size_t)(c + 0) * DIM + r]     = v0;
                C[(size_t)(c + 1) * DIM + r]     = v1;
                C[(size_t)(c + 0) * DIM + r + 8] = v2;
                C[(size_t)(c + 1) * DIM + r + 8] = v3;
            }
        }
    }
}

// ---------------------------------------------------------------------------
// block-local matvec for 512 threads: ws = Mb @ xs (256x256).
// 16 warps, warp handles 4 rows/pass (8 lanes per row), 4 passes.
// ---------------------------------------------------------------------------
__device__ __forceinline__ void block_matvec512(const float* __restrict__ Mb,
                                                const float* __restrict__ xs,
                                                float* __restrict__ ws, int tid) {
    int warp = tid >> 5, lane = tid & 31;
    #pragma unroll
    for (int pass = 0; pass < 4; ++pass) {
        int r = pass * 64 + warp * 4 + (lane >> 3);
        int c0 = (lane & 7) * 32;
        const float* Mr = Mb + (size_t)r * DIM + c0;
        float s = 0.f;
        #pragma unroll
        for (int c = 0; c < 32; c += 4) {
            float4 mv = *(const float4*)(Mr + c);
            s += mv.x * xs[c0 + c] + mv.y * xs[c0 + c + 1]
               + mv.z * xs[c0 + c + 2] + mv.w * xs[c0 + c + 3];
        }
        #pragma unroll
        for (int o = 4; o; o >>= 1) s += __shfl_xor_sync(0xffffffffu, s, o);
        if ((lane & 7) == 0) ws[r] = s;
    }
}

// M2-chain: t1 = M2 x, t2 = M2 t1, t3 = M2 t2  (call with syncthreads around)
#define M2_CHAIN(xsrc)                                              \
    block_matvec512(M2b, xsrc, t1, tid); __syncthreads();           \
    block_matvec512(M2b, t1,   t2, tid); __syncthreads();           \
    block_matvec512(M2b, t2,   t3, tid); __syncthreads();

// ---------------------------------------------------------------------------
// fused vector pipeline: one 512-thread block per batch. M3 never materialized:
// M3 x = 2.25 t1 - 1.5 t2 + 0.25 t3 with t's = M2-chain of x.
// ---------------------------------------------------------------------------
__global__ void __launch_bounds__(512) tail_kernel(const float* __restrict__ A,
                                                   const float* __restrict__ M1,
                                                   const float* __restrict__ M2,
                                                   float* __restrict__ out) {
    int b = blockIdx.x, tid = threadIdx.x;
    __shared__ float v[DIM], t1[DIM], t2[DIM], t3[DIM], w1[DIM], w2[DIM];
    const float* Ab  = A  + (size_t)b * DD;
    const float* M1b = M1 + (size_t)b * DD;
    const float* M2b = M2 + (size_t)b * DD;
    if (tid < DIM) v[tid] = g_mean[b * DIM + tid];
    __syncthreads();
    // v-updates with A, M1, M2
    block_matvec512(Ab,  v, t1, tid); __syncthreads();
    if (tid < DIM) v[tid] = 1.5f * v[tid] - 0.5f * t1[tid];
    __syncthreads();
    block_matvec512(M1b, v, t1, tid); __syncthreads();
    if (tid < DIM) v[tid] = 1.5f * v[tid] - 0.5f * t1[tid];
    __syncthreads();
    block_matvec512(M2b, v, t1, tid); __syncthreads();
    if (tid < DIM) v[tid] = 1.5f * v[tid] - 0.5f * t1[tid];
    __syncthreads();
    // v-update with M3 (virtual): v = 1.5v - 0.5*M3 v
    M2_CHAIN(v);
    if (tid < DIM)
        v[tid] = 1.5f * v[tid] - 1.125f * t1[tid] + 0.75f * t2[tid] - 0.125f * t3[tid];
    __syncthreads();
    // w1 = M3 v
    M2_CHAIN(v);
    if (tid < DIM) w1[tid] = 2.25f * t1[tid] - 1.5f * t2[tid] + 0.25f * t3[tid];
    __syncthreads();
    // w2 = M3 w1
    M2_CHAIN(w1);
    if (tid < DIM) w2[tid] = 2.25f * t1[tid] - 1.5f * t2[tid] + 0.25f * t3[tid];
    __syncthreads();
    // w3 = M3 w2, folded directly into the final combine:
    // x5 = 1.5v - 1.125w1 + 0.75w2 - 0.125*w3
    //    = 1.5v - 1.125w1 + 0.75w2 - 0.28125t1 + 0.1875t2 - 0.03125t3
    M2_CHAIN(w2);
    if (tid < DIM)
        v[tid] = 1.5f * v[tid] - 1.125f * w1[tid] + 0.75f * w2[tid]
               - 0.28125f * t1[tid] + 0.1875f * t2[tid] - 0.03125f * t3[tid];
    __syncthreads();
    // out = sqrt(norm) * A @ x5
    block_matvec512(Ab, v, t1, tid); __syncthreads();
    if (tid < DIM) out[b * DIM + tid] = sqrtf(g_norm[b]) * t1[tid];
}

// ---------------------------------------------------------------------------
extern "C" void kernel_launch(void* const* d_in, const int* in_sizes, int n_in,
                              void* d_out, int out_size) {
    const float* feat  = (const float*)d_in[0];
    const float* noise = (const float*)d_in[1];
    float* out = (float*)d_out;

    float *A, *DTh, *DTm, *X2, *M1, *M2;
    cudaGetSymbolAddress((void**)&A,    g_A);
    cudaGetSymbolAddress((void**)&DTh,  g_DTh);
    cudaGetSymbolAddress((void**)&DTm,  g_DTm);
    cudaGetSymbolAddress((void**)&X2,   g_X2);
    cudaGetSymbolAddress((void**)&M1,   g_M1);
    cudaGetSymbolAddress((void**)&M2,   g_M2);

    mean_part<<<dim3(4, NB), 256>>>(feat, noise);
    mean_final<<<NB, 256>>>();
    prep_kernel<<<dim3(NPG / 32, DIM / 32, NB), 256>>>(feat, noise,
        (__nv_bfloat16*)DTh, (__nv_bfloat16*)DTm);
    cov_mma<<<dim3(6, 1, NB), 256>>>(
        (const __nv_bfloat16*)DTh, (const __nv_bfloat16*)DTm, A);

    // 2 NS matrix iterations only: M1 = f(A), M2 = f(M1)
    dim3 gg(6, 1, NB);
    gemm_bf16<<<gg, 256>>>(A,  A,  X2, A,  A,  0);
    gemm_bf16<<<gg, 256>>>(X2, A,  M1, A,  X2, 1);
    gemm_bf16<<<gg, 256>>>(M1, M1, X2, A,  A,  0);
    gemm_bf16<<<gg, 256>>>(X2, M1, M2, M1, X2, 1);

    // all remaining algebra (M3 virtualized) in ONE launch
    tail_kernel<<<NB, 512>>>(A, M1, M2, out);
}